// round 5
// baseline (speedup 1.0000x reference)
#include <cuda_runtime.h>
#include <cuda_bf16.h>
#include <cstdint>

// Problem constants
#define BB 8
#define CC 256
#define HH 112
#define HWSZ 12544              // 112*112
#define ELEMS_PER_IMG (CC * HWSZ)       // 3,211,264
#define TOTAL_ELEMS (BB * ELEMS_PER_IMG) // 25,690,112

// Scratch (device globals; no allocations allowed)
__device__ float g_Q[TOTAL_ELEMS];
__device__ float g_K[TOTAL_ELEMS];
__device__ float g_V[TOTAL_ELEMS];
__device__ float g_Zs[TOTAL_ELEMS];

// ---------------------------------------------------------------------------
// GEMM: out[b,o,s] = sum_c W[o,c] * in[b,c,s]  (+ optional residual + relu)
// W: [256,256] row-major. in/out: [B, C, HW].
// Block tile 128x128x8, 256 threads, 8x8 per thread (split 4+4 in each dim).
// ---------------------------------------------------------------------------
__global__ void __launch_bounds__(256, 2)
gemm_conv_kernel(const float* __restrict__ Wmat,
                 const float* __restrict__ in,
                 const float* __restrict__ res,
                 float* __restrict__ out,
                 int do_relu)
{
    __shared__ float As[8][128];   // transposed W tile: As[k][m]
    __shared__ float Bs[8][128];   // Bs[k][n]

    const int b  = blockIdx.z;
    const int m0 = blockIdx.y * 128;
    const int n0 = blockIdx.x * 128;
    const float* inb  = in  + (size_t)b * ELEMS_PER_IMG;
    float*       outb = out + (size_t)b * ELEMS_PER_IMG;

    const int tid  = threadIdx.x;
    const int tRow = tid >> 4;     // 0..15
    const int tCol = tid & 15;     // 0..15

    // A load: 128x8 tile = 1024 floats; each thread: one float4
    const int aRow = tid >> 1;          // 0..127
    const int aCol = (tid & 1) * 4;     // 0 or 4
    // B load: 8x128 tile; each thread: one float4
    const int bRow = tid >> 5;          // 0..7
    const int bCol = (tid & 31) * 4;    // 0..124

    float acc[8][8];
#pragma unroll
    for (int i = 0; i < 8; i++)
#pragma unroll
        for (int j = 0; j < 8; j++) acc[i][j] = 0.0f;

    for (int kk = 0; kk < CC; kk += 8) {
        float4 av = *reinterpret_cast<const float4*>(&Wmat[(m0 + aRow) * CC + kk + aCol]);
        As[aCol + 0][aRow] = av.x;
        As[aCol + 1][aRow] = av.y;
        As[aCol + 2][aRow] = av.z;
        As[aCol + 3][aRow] = av.w;
        *reinterpret_cast<float4*>(&Bs[bRow][bCol]) =
            *reinterpret_cast<const float4*>(&inb[(size_t)(kk + bRow) * HWSZ + n0 + bCol]);
        __syncthreads();
#pragma unroll
        for (int k = 0; k < 8; ++k) {
            float a[8], bv[8];
            *reinterpret_cast<float4*>(&a[0]) = *reinterpret_cast<float4*>(&As[k][tRow * 4]);
            *reinterpret_cast<float4*>(&a[4]) = *reinterpret_cast<float4*>(&As[k][tRow * 4 + 64]);
            *reinterpret_cast<float4*>(&bv[0]) = *reinterpret_cast<float4*>(&Bs[k][tCol * 4]);
            *reinterpret_cast<float4*>(&bv[4]) = *reinterpret_cast<float4*>(&Bs[k][tCol * 4 + 64]);
#pragma unroll
            for (int i = 0; i < 8; i++)
#pragma unroll
                for (int j = 0; j < 8; j++)
                    acc[i][j] += a[i] * bv[j];
        }
        __syncthreads();
    }

    const float* resb = res ? res + (size_t)b * ELEMS_PER_IMG : nullptr;

#pragma unroll
    for (int ih = 0; ih < 2; ih++) {
#pragma unroll
        for (int i = 0; i < 4; i++) {
            const int m = m0 + tRow * 4 + ih * 64 + i;
#pragma unroll
            for (int jh = 0; jh < 2; jh++) {
                const int n = n0 + tCol * 4 + jh * 64;
                float4 v;
                v.x = acc[ih * 4 + i][jh * 4 + 0];
                v.y = acc[ih * 4 + i][jh * 4 + 1];
                v.z = acc[ih * 4 + i][jh * 4 + 2];
                v.w = acc[ih * 4 + i][jh * 4 + 3];
                if (do_relu) {
                    float4 r = *reinterpret_cast<const float4*>(&resb[(size_t)m * HWSZ + n]);
                    v.x = fmaxf(v.x + r.x, 0.0f);
                    v.y = fmaxf(v.y + r.y, 0.0f);
                    v.z = fmaxf(v.z + r.z, 0.0f);
                    v.w = fmaxf(v.w + r.w, 0.0f);
                }
                *reinterpret_cast<float4*>(&outb[(size_t)m * HWSZ + n]) = v;
            }
        }
    }
}

// ---------------------------------------------------------------------------
// Attention per (b,c): scores = Q@K -> softmax(rows) -> Z = M@V
// One block per (b,c). Q/K/V tiles (112x112 each) fully resident in smem.
// 256 threads = 16x16, each thread owns a 7x7 output micro-tile.
// Softmax row reductions via 16-lane shuffle segments.
// ---------------------------------------------------------------------------
__global__ void __launch_bounds__(256, 1)
attn_kernel(const float* __restrict__ Q, const float* __restrict__ K,
            const float* __restrict__ V, float* __restrict__ Z)
{
    extern __shared__ float sm[];
    float* Qs = sm;              // 12544 floats; reused for M, then staging is Ks
    float* Ks = sm + HWSZ;
    float* Vs = sm + 2 * HWSZ;

    const size_t base = (size_t)blockIdx.x * HWSZ;
    const int tid = threadIdx.x;

    // Coalesced float4 loads (12544/4 = 3136 per tensor)
    {
        const float4* Qg = reinterpret_cast<const float4*>(Q + base);
        const float4* Kg = reinterpret_cast<const float4*>(K + base);
        const float4* Vg = reinterpret_cast<const float4*>(V + base);
        float4* Q4 = reinterpret_cast<float4*>(Qs);
        float4* K4 = reinterpret_cast<float4*>(Ks);
        float4* V4 = reinterpret_cast<float4*>(Vs);
        for (int i = tid; i < HWSZ / 4; i += 256) {
            Q4[i] = Qg[i];
            K4[i] = Kg[i];
            V4[i] = Vg[i];
        }
    }
    __syncthreads();

    const int ty = tid >> 4;      // 0..15
    const int tx = tid & 15;      // 0..15
    const int i0 = ty * 7;
    const int j0 = tx * 7;

    float acc[7][7];
#pragma unroll
    for (int r = 0; r < 7; r++)
#pragma unroll
        for (int c = 0; c < 7; c++) acc[r][c] = 0.0f;

    // scores[i][j] = sum_k Q[i][k] * K[k][j]
    for (int k = 0; k < HH; ++k) {
        float qr[7], kc[7];
#pragma unroll
        for (int r = 0; r < 7; r++) qr[r] = Qs[(i0 + r) * HH + k];
#pragma unroll
        for (int c = 0; c < 7; c++) kc[c] = Ks[k * HH + j0 + c];
#pragma unroll
        for (int r = 0; r < 7; r++)
#pragma unroll
            for (int c = 0; c < 7; c++) acc[r][c] += qr[r] * kc[c];
    }

    // Row softmax: reduce over j (across the 16 tx lanes, which sit in a
    // 16-lane contiguous segment of the warp).
#pragma unroll
    for (int r = 0; r < 7; r++) {
        float mx = acc[r][0];
#pragma unroll
        for (int c = 1; c < 7; c++) mx = fmaxf(mx, acc[r][c]);
#pragma unroll
        for (int ofs = 1; ofs < 16; ofs <<= 1)
            mx = fmaxf(mx, __shfl_xor_sync(0xffffffffu, mx, ofs));
        float s = 0.0f;
#pragma unroll
        for (int c = 0; c < 7; c++) {
            acc[r][c] = __expf(acc[r][c] - mx);
            s += acc[r][c];
        }
#pragma unroll
        for (int ofs = 1; ofs < 16; ofs <<= 1)
            s += __shfl_xor_sync(0xffffffffu, s, ofs);
        const float inv = 1.0f / s;
#pragma unroll
        for (int c = 0; c < 7; c++) acc[r][c] *= inv;
    }

    __syncthreads();   // everyone done reading Qs before overwrite with M
#pragma unroll
    for (int r = 0; r < 7; r++)
#pragma unroll
        for (int c = 0; c < 7; c++)
            Qs[(i0 + r) * HH + j0 + c] = acc[r][c];
    __syncthreads();

    // Z = M @ V   (reuse acc registers)
#pragma unroll
    for (int r = 0; r < 7; r++)
#pragma unroll
        for (int c = 0; c < 7; c++) acc[r][c] = 0.0f;

    for (int k = 0; k < HH; ++k) {
        float mr[7], vc[7];
#pragma unroll
        for (int r = 0; r < 7; r++) mr[r] = Qs[(i0 + r) * HH + k];
#pragma unroll
        for (int c = 0; c < 7; c++) vc[c] = Vs[k * HH + j0 + c];
#pragma unroll
        for (int r = 0; r < 7; r++)
#pragma unroll
            for (int c = 0; c < 7; c++) acc[r][c] += mr[r] * vc[c];
    }

    // Stage Z through smem (Ks is dead) for coalesced global stores
    __syncthreads();
#pragma unroll
    for (int r = 0; r < 7; r++)
#pragma unroll
        for (int c = 0; c < 7; c++)
            Ks[(i0 + r) * HH + j0 + c] = acc[r][c];
    __syncthreads();
    {
        const float4* K4 = reinterpret_cast<const float4*>(Ks);
        float4* Zg = reinterpret_cast<float4*>(Z + base);
        for (int i = tid; i < HWSZ / 4; i += 256) Zg[i] = K4[i];
    }
}

extern "C" void kernel_launch(void* const* d_in, const int* in_sizes, int n_in,
                              void* d_out, int out_size)
{
    const float* x  = (const float*)d_in[0];
    const float* y  = (const float*)d_in[1];
    const float* WQ = (const float*)d_in[2];
    const float* WK = (const float*)d_in[3];
    const float* WV = (const float*)d_in[4];
    const float* WZ = (const float*)d_in[5];
    float* out = (float*)d_out;

    float *dQ, *dK, *dV, *dZ;
    cudaGetSymbolAddress((void**)&dQ, g_Q);
    cudaGetSymbolAddress((void**)&dK, g_K);
    cudaGetSymbolAddress((void**)&dV, g_V);
    cudaGetSymbolAddress((void**)&dZ, g_Zs);

    const int attn_smem = 3 * HWSZ * (int)sizeof(float);   // 150,528 B
    cudaFuncSetAttribute(attn_kernel, cudaFuncAttributeMaxDynamicSharedMemorySize,
                         attn_smem);

    dim3 gg(HWSZ / 128, CC / 128, BB);   // (98, 2, 8)

    gemm_conv_kernel<<<gg, 256>>>(WQ, x, nullptr, dQ, 0);
    gemm_conv_kernel<<<gg, 256>>>(WK, y, nullptr, dK, 0);
    gemm_conv_kernel<<<gg, 256>>>(WV, y, nullptr, dV, 0);
    attn_kernel<<<BB * CC, 256, attn_smem>>>(dQ, dK, dV, dZ);
    gemm_conv_kernel<<<gg, 256>>>(WZ, dZ, x, out, 1);
}

// round 7
// speedup vs baseline: 1.3638x; 1.3638x over previous
#include <cuda_runtime.h>
#include <cuda_bf16.h>
#include <cstdint>

// Problem constants
#define BB 8
#define CC 256
#define HH 112
#define HWSZ 12544              // 112*112
#define ELEMS_PER_IMG (CC * HWSZ)
#define TOTAL_ELEMS (BB * ELEMS_PER_IMG)

// Scratch (device globals; no allocations allowed)
__device__ float g_Q[TOTAL_ELEMS];
__device__ float g_K[TOTAL_ELEMS];
__device__ float g_V[TOTAL_ELEMS];
__device__ float g_Zs[TOTAL_ELEMS];

__device__ __forceinline__ uint32_t f2tf32(float f) {
    uint32_t r;
    asm("cvt.rna.tf32.f32 %0, %1;" : "=r"(r) : "f"(f));
    return r;
}

// mma.sync m16n8k8 tf32 (baseline PTX, works on compute_103 / legacy HMMA pipe)
__device__ __forceinline__ void mma_tf32(float* c, const uint32_t* a, const uint32_t* b) {
    asm volatile(
        "mma.sync.aligned.m16n8k8.row.col.f32.tf32.tf32.f32 "
        "{%0,%1,%2,%3}, {%4,%5,%6,%7}, {%8,%9}, {%0,%1,%2,%3};"
        : "+f"(c[0]), "+f"(c[1]), "+f"(c[2]), "+f"(c[3])
        : "r"(a[0]), "r"(a[1]), "r"(a[2]), "r"(a[3]), "r"(b[0]), "r"(b[1]));
}

// ============================================================================
// tf32 tensor-core GEMM: out[b,o,s] = sum_c W[o,c] * in[b,c,s] (+res+relu)
// CTA: 512 threads (16 warps, 4x4), tile M=128 (o), N=128 (s), K=256.
// K-chunks of 32, double-buffered smem, 1 sync per chunk.
//   A smem [m][k]  pitch 36 floats (conflict-free for frag quads)
//   B smem [k][n]  pitch 136 floats (conflict-free)
// Warp tile 32x32: 2 m-frags x 4 n-frags.
// ============================================================================
#define PA 36
#define PB 136
#define A_BYTES (128 * PA * 4)        // 18432
#define B_BYTES (32 * PB * 4)         // 17408
#define GEMM_SMEM (2 * (A_BYTES + B_BYTES))  // 71680

__global__ void __launch_bounds__(512, 1)
gemm_tc_kernel(const float* __restrict__ Wmat,
               const float* __restrict__ in,
               const float* __restrict__ res,
               float* __restrict__ out,
               int do_relu)
{
    extern __shared__ char smraw[];
    uint32_t* Abuf[2] = { reinterpret_cast<uint32_t*>(smraw),
                          reinterpret_cast<uint32_t*>(smraw + A_BYTES) };
    uint32_t* Bbuf[2] = { reinterpret_cast<uint32_t*>(smraw + 2 * A_BYTES),
                          reinterpret_cast<uint32_t*>(smraw + 2 * A_BYTES + B_BYTES) };

    const int tid  = threadIdx.x;
    const int wid  = tid >> 5;
    const int lane = tid & 31;
    const int g    = lane >> 2;     // group id 0..7
    const int t    = lane & 3;      // thread-in-group 0..3
    const int wm   = (wid >> 2) * 32;
    const int wn   = (wid & 3) * 32;

    const int m0 = blockIdx.x * 128;
    const int n0 = blockIdx.y * 128;
    const int b  = blockIdx.z;
    const float* inb  = in  + (size_t)b * ELEMS_PER_IMG;
    float*       outb = out + (size_t)b * ELEMS_PER_IMG;

    // staging indices (each thread moves 2 float4 for A, 2 for B)
    const int fa0 = tid, fa1 = tid + 512;          // A slots: m=f>>3, k4=f&7
    const int fb0 = tid, fb1 = tid + 512;          // B slots: k=f>>5, n4=f&31

    float acc[2][4][4];
#pragma unroll
    for (int i = 0; i < 2; i++)
#pragma unroll
        for (int j = 0; j < 4; j++)
#pragma unroll
            for (int e = 0; e < 4; e++) acc[i][j][e] = 0.0f;

    // ---- prologue: chunk 0 ----
    float4 sA0, sA1, sB0, sB1;
    sA0 = *reinterpret_cast<const float4*>(&Wmat[(m0 + (fa0 >> 3)) * CC + (fa0 & 7) * 4]);
    sA1 = *reinterpret_cast<const float4*>(&Wmat[(m0 + (fa1 >> 3)) * CC + (fa1 & 7) * 4]);
    sB0 = *reinterpret_cast<const float4*>(&inb[(size_t)(fb0 >> 5) * HWSZ + n0 + (fb0 & 31) * 4]);
    sB1 = *reinterpret_cast<const float4*>(&inb[(size_t)(fb1 >> 5) * HWSZ + n0 + (fb1 & 31) * 4]);
    {
        uint32_t* Ad = Abuf[0];
        uint32_t* Bd = Bbuf[0];
        Ad[(fa0 >> 3) * PA + (fa0 & 7) * 4 + 0] = f2tf32(sA0.x);
        Ad[(fa0 >> 3) * PA + (fa0 & 7) * 4 + 1] = f2tf32(sA0.y);
        Ad[(fa0 >> 3) * PA + (fa0 & 7) * 4 + 2] = f2tf32(sA0.z);
        Ad[(fa0 >> 3) * PA + (fa0 & 7) * 4 + 3] = f2tf32(sA0.w);
        Ad[(fa1 >> 3) * PA + (fa1 & 7) * 4 + 0] = f2tf32(sA1.x);
        Ad[(fa1 >> 3) * PA + (fa1 & 7) * 4 + 1] = f2tf32(sA1.y);
        Ad[(fa1 >> 3) * PA + (fa1 & 7) * 4 + 2] = f2tf32(sA1.z);
        Ad[(fa1 >> 3) * PA + (fa1 & 7) * 4 + 3] = f2tf32(sA1.w);
        Bd[(fb0 >> 5) * PB + (fb0 & 31) * 4 + 0] = f2tf32(sB0.x);
        Bd[(fb0 >> 5) * PB + (fb0 & 31) * 4 + 1] = f2tf32(sB0.y);
        Bd[(fb0 >> 5) * PB + (fb0 & 31) * 4 + 2] = f2tf32(sB0.z);
        Bd[(fb0 >> 5) * PB + (fb0 & 31) * 4 + 3] = f2tf32(sB0.w);
        Bd[(fb1 >> 5) * PB + (fb1 & 31) * 4 + 0] = f2tf32(sB1.x);
        Bd[(fb1 >> 5) * PB + (fb1 & 31) * 4 + 1] = f2tf32(sB1.y);
        Bd[(fb1 >> 5) * PB + (fb1 & 31) * 4 + 2] = f2tf32(sB1.z);
        Bd[(fb1 >> 5) * PB + (fb1 & 31) * 4 + 3] = f2tf32(sB1.w);
    }
    __syncthreads();

    for (int i = 0; i < 8; ++i) {
        const int p = i & 1;

        // prefetch next chunk (global -> regs) to overlap with compute
        if (i < 7) {
            const int kk2 = (i + 1) * 32;
            sA0 = *reinterpret_cast<const float4*>(&Wmat[(m0 + (fa0 >> 3)) * CC + kk2 + (fa0 & 7) * 4]);
            sA1 = *reinterpret_cast<const float4*>(&Wmat[(m0 + (fa1 >> 3)) * CC + kk2 + (fa1 & 7) * 4]);
            sB0 = *reinterpret_cast<const float4*>(&inb[(size_t)(kk2 + (fb0 >> 5)) * HWSZ + n0 + (fb0 & 31) * 4]);
            sB1 = *reinterpret_cast<const float4*>(&inb[(size_t)(kk2 + (fb1 >> 5)) * HWSZ + n0 + (fb1 & 31) * 4]);
        }

        // compute chunk i from buffer p
        const uint32_t* As = Abuf[p];
        const uint32_t* Bs = Bbuf[p];
#pragma unroll
        for (int ks = 0; ks < 4; ++ks) {
            uint32_t afr[2][4], bfr[4][2];
#pragma unroll
            for (int f = 0; f < 2; ++f) {
                const int row = wm + f * 16 + g;
                afr[f][0] = As[row * PA + ks * 8 + t];
                afr[f][1] = As[(row + 8) * PA + ks * 8 + t];
                afr[f][2] = As[row * PA + ks * 8 + t + 4];
                afr[f][3] = As[(row + 8) * PA + ks * 8 + t + 4];
            }
#pragma unroll
            for (int j = 0; j < 4; ++j) {
                const int col = wn + j * 8 + g;
                bfr[j][0] = Bs[(ks * 8 + t) * PB + col];
                bfr[j][1] = Bs[(ks * 8 + t + 4) * PB + col];
            }
#pragma unroll
            for (int f = 0; f < 2; ++f)
#pragma unroll
                for (int j = 0; j < 4; ++j)
                    mma_tf32(acc[f][j], afr[f], bfr[j]);
        }

        // store prefetched chunk into the other buffer
        if (i < 7) {
            uint32_t* Ad = Abuf[p ^ 1];
            uint32_t* Bd = Bbuf[p ^ 1];
            Ad[(fa0 >> 3) * PA + (fa0 & 7) * 4 + 0] = f2tf32(sA0.x);
            Ad[(fa0 >> 3) * PA + (fa0 & 7) * 4 + 1] = f2tf32(sA0.y);
            Ad[(fa0 >> 3) * PA + (fa0 & 7) * 4 + 2] = f2tf32(sA0.z);
            Ad[(fa0 >> 3) * PA + (fa0 & 7) * 4 + 3] = f2tf32(sA0.w);
            Ad[(fa1 >> 3) * PA + (fa1 & 7) * 4 + 0] = f2tf32(sA1.x);
            Ad[(fa1 >> 3) * PA + (fa1 & 7) * 4 + 1] = f2tf32(sA1.y);
            Ad[(fa1 >> 3) * PA + (fa1 & 7) * 4 + 2] = f2tf32(sA1.z);
            Ad[(fa1 >> 3) * PA + (fa1 & 7) * 4 + 3] = f2tf32(sA1.w);
            Bd[(fb0 >> 5) * PB + (fb0 & 31) * 4 + 0] = f2tf32(sB0.x);
            Bd[(fb0 >> 5) * PB + (fb0 & 31) * 4 + 1] = f2tf32(sB0.y);
            Bd[(fb0 >> 5) * PB + (fb0 & 31) * 4 + 2] = f2tf32(sB0.z);
            Bd[(fb0 >> 5) * PB + (fb0 & 31) * 4 + 3] = f2tf32(sB0.w);
            Bd[(fb1 >> 5) * PB + (fb1 & 31) * 4 + 0] = f2tf32(sB1.x);
            Bd[(fb1 >> 5) * PB + (fb1 & 31) * 4 + 1] = f2tf32(sB1.y);
            Bd[(fb1 >> 5) * PB + (fb1 & 31) * 4 + 2] = f2tf32(sB1.z);
            Bd[(fb1 >> 5) * PB + (fb1 & 31) * 4 + 3] = f2tf32(sB1.w);
        }
        __syncthreads();
    }

    // ---- epilogue: C frags -> global (float2 per row segment) ----
    const float* resb = res ? res + (size_t)b * ELEMS_PER_IMG : nullptr;
#pragma unroll
    for (int f = 0; f < 2; ++f) {
#pragma unroll
        for (int j = 0; j < 4; ++j) {
            const int row = m0 + wm + f * 16 + g;
            const int col = n0 + wn + j * 8 + 2 * t;
            float2 v0 = { acc[f][j][0], acc[f][j][1] };
            float2 v1 = { acc[f][j][2], acc[f][j][3] };
            if (do_relu) {
                float2 r0 = *reinterpret_cast<const float2*>(&resb[(size_t)row * HWSZ + col]);
                float2 r1 = *reinterpret_cast<const float2*>(&resb[(size_t)(row + 8) * HWSZ + col]);
                v0.x = fmaxf(v0.x + r0.x, 0.0f);
                v0.y = fmaxf(v0.y + r0.y, 0.0f);
                v1.x = fmaxf(v1.x + r1.x, 0.0f);
                v1.y = fmaxf(v1.y + r1.y, 0.0f);
            }
            *reinterpret_cast<float2*>(&outb[(size_t)row * HWSZ + col]) = v0;
            *reinterpret_cast<float2*>(&outb[(size_t)(row + 8) * HWSZ + col]) = v1;
        }
    }
}

// ---------------------------------------------------------------------------
// Attention per (b,c): unchanged from the 479us passing version.
// ---------------------------------------------------------------------------
__global__ void __launch_bounds__(256, 1)
attn_kernel(const float* __restrict__ Q, const float* __restrict__ K,
            const float* __restrict__ V, float* __restrict__ Z)
{
    extern __shared__ float smf[];
    float* Qs = smf;
    float* Ks = smf + HWSZ;
    float* Vs = smf + 2 * HWSZ;

    const size_t base = (size_t)blockIdx.x * HWSZ;
    const int tid = threadIdx.x;

    {
        const float4* Qg = reinterpret_cast<const float4*>(Q + base);
        const float4* Kg = reinterpret_cast<const float4*>(K + base);
        const float4* Vg = reinterpret_cast<const float4*>(V + base);
        float4* Q4 = reinterpret_cast<float4*>(Qs);
        float4* K4 = reinterpret_cast<float4*>(Ks);
        float4* V4 = reinterpret_cast<float4*>(Vs);
        for (int i = tid; i < HWSZ / 4; i += 256) {
            Q4[i] = Qg[i];
            K4[i] = Kg[i];
            V4[i] = Vg[i];
        }
    }
    __syncthreads();

    const int ty = tid >> 4;
    const int tx = tid & 15;
    const int i0 = ty * 7;
    const int j0 = tx * 7;

    float acc[7][7];
#pragma unroll
    for (int r = 0; r < 7; r++)
#pragma unroll
        for (int c = 0; c < 7; c++) acc[r][c] = 0.0f;

    for (int k = 0; k < HH; ++k) {
        float qr[7], kc[7];
#pragma unroll
        for (int r = 0; r < 7; r++) qr[r] = Qs[(i0 + r) * HH + k];
#pragma unroll
        for (int c = 0; c < 7; c++) kc[c] = Ks[k * HH + j0 + c];
#pragma unroll
        for (int r = 0; r < 7; r++)
#pragma unroll
            for (int c = 0; c < 7; c++) acc[r][c] += qr[r] * kc[c];
    }

#pragma unroll
    for (int r = 0; r < 7; r++) {
        float mx = acc[r][0];
#pragma unroll
        for (int c = 1; c < 7; c++) mx = fmaxf(mx, acc[r][c]);
#pragma unroll
        for (int ofs = 1; ofs < 16; ofs <<= 1)
            mx = fmaxf(mx, __shfl_xor_sync(0xffffffffu, mx, ofs));
        float s = 0.0f;
#pragma unroll
        for (int c = 0; c < 7; c++) {
            acc[r][c] = __expf(acc[r][c] - mx);
            s += acc[r][c];
        }
#pragma unroll
        for (int ofs = 1; ofs < 16; ofs <<= 1)
            s += __shfl_xor_sync(0xffffffffu, s, ofs);
        const float inv = 1.0f / s;
#pragma unroll
        for (int c = 0; c < 7; c++) acc[r][c] *= inv;
    }

    __syncthreads();
#pragma unroll
    for (int r = 0; r < 7; r++)
#pragma unroll
        for (int c = 0; c < 7; c++)
            Qs[(i0 + r) * HH + j0 + c] = acc[r][c];
    __syncthreads();

#pragma unroll
    for (int r = 0; r < 7; r++)
#pragma unroll
        for (int c = 0; c < 7; c++) acc[r][c] = 0.0f;

    for (int k = 0; k < HH; ++k) {
        float mr[7], vc[7];
#pragma unroll
        for (int r = 0; r < 7; r++) mr[r] = Qs[(i0 + r) * HH + k];
#pragma unroll
        for (int c = 0; c < 7; c++) vc[c] = Vs[k * HH + j0 + c];
#pragma unroll
        for (int r = 0; r < 7; r++)
#pragma unroll
            for (int c = 0; c < 7; c++) acc[r][c] += mr[r] * vc[c];
    }

    __syncthreads();
#pragma unroll
    for (int r = 0; r < 7; r++)
#pragma unroll
        for (int c = 0; c < 7; c++)
            Ks[(i0 + r) * HH + j0 + c] = acc[r][c];
    __syncthreads();
    {
        const float4* K4 = reinterpret_cast<const float4*>(Ks);
        float4* Zg = reinterpret_cast<float4*>(Z + base);
        for (int i = tid; i < HWSZ / 4; i += 256) Zg[i] = K4[i];
    }
}

extern "C" void kernel_launch(void* const* d_in, const int* in_sizes, int n_in,
                              void* d_out, int out_size)
{
    const float* x  = (const float*)d_in[0];
    const float* y  = (const float*)d_in[1];
    const float* WQ = (const float*)d_in[2];
    const float* WK = (const float*)d_in[3];
    const float* WV = (const float*)d_in[4];
    const float* WZ = (const float*)d_in[5];
    float* out = (float*)d_out;

    float *dQ, *dK, *dV, *dZ;
    cudaGetSymbolAddress((void**)&dQ, g_Q);
    cudaGetSymbolAddress((void**)&dK, g_K);
    cudaGetSymbolAddress((void**)&dV, g_V);
    cudaGetSymbolAddress((void**)&dZ, g_Zs);

    const int attn_smem = 3 * HWSZ * (int)sizeof(float);   // 150,528 B
    cudaFuncSetAttribute(attn_kernel, cudaFuncAttributeMaxDynamicSharedMemorySize,
                         attn_smem);
    cudaFuncSetAttribute(gemm_tc_kernel, cudaFuncAttributeMaxDynamicSharedMemorySize,
                         GEMM_SMEM);

    dim3 gg(2, HWSZ / 128, BB);   // m-tile fastest -> B-tile L2 reuse, (2, 98, 8)

    gemm_tc_kernel<<<gg, 512, GEMM_SMEM>>>(WQ, x, nullptr, dQ, 0);
    gemm_tc_kernel<<<gg, 512, GEMM_SMEM>>>(WK, y, nullptr, dK, 0);
    gemm_tc_kernel<<<gg, 512, GEMM_SMEM>>>(WV, y, nullptr, dV, 0);
    attn_kernel<<<BB * CC, 256, attn_smem>>>(dQ, dK, dV, dZ);
    gemm_tc_kernel<<<gg, 512, GEMM_SMEM>>>(WZ, dZ, x, out, 1);
}

// round 8
// speedup vs baseline: 1.7359x; 1.2728x over previous
#include <cuda_runtime.h>
#include <cuda_bf16.h>
#include <cstdint>

// Problem constants
#define BB 8
#define CC 256
#define HH 112
#define HWSZ 12544              // 112*112
#define ELEMS_PER_IMG (CC * HWSZ)
#define TOTAL_ELEMS (BB * ELEMS_PER_IMG)

// Scratch (device globals; no allocations allowed)
__device__ float g_Q[TOTAL_ELEMS];
__device__ float g_K[TOTAL_ELEMS];
__device__ float g_V[TOTAL_ELEMS];
__device__ float g_Zs[TOTAL_ELEMS];

__device__ __forceinline__ uint32_t f2tf32(float f) {
    uint32_t r;
    asm("cvt.rna.tf32.f32 %0, %1;" : "=r"(r) : "f"(f));
    return r;
}

// mma.sync m16n8k8 tf32 (baseline PTX; validated in R7)
__device__ __forceinline__ void mma_tf32(float* c, const uint32_t* a, const uint32_t* b) {
    asm volatile(
        "mma.sync.aligned.m16n8k8.row.col.f32.tf32.tf32.f32 "
        "{%0,%1,%2,%3}, {%4,%5,%6,%7}, {%8,%9}, {%0,%1,%2,%3};"
        : "+f"(c[0]), "+f"(c[1]), "+f"(c[2]), "+f"(c[3])
        : "r"(a[0]), "r"(a[1]), "r"(a[2]), "r"(a[3]), "r"(b[0]), "r"(b[1]));
}

// ============================================================================
// tf32 tensor-core GEMM (unchanged from R7 passing version)
// ============================================================================
#define PA 36
#define PB 136
#define A_BYTES (128 * PA * 4)
#define B_BYTES (32 * PB * 4)
#define GEMM_SMEM (2 * (A_BYTES + B_BYTES))

__global__ void __launch_bounds__(512, 1)
gemm_tc_kernel(const float* __restrict__ Wmat,
               const float* __restrict__ in,
               const float* __restrict__ res,
               float* __restrict__ out,
               int do_relu)
{
    extern __shared__ char smraw[];
    uint32_t* Abuf[2] = { reinterpret_cast<uint32_t*>(smraw),
                          reinterpret_cast<uint32_t*>(smraw + A_BYTES) };
    uint32_t* Bbuf[2] = { reinterpret_cast<uint32_t*>(smraw + 2 * A_BYTES),
                          reinterpret_cast<uint32_t*>(smraw + 2 * A_BYTES + B_BYTES) };

    const int tid  = threadIdx.x;
    const int wid  = tid >> 5;
    const int lane = tid & 31;
    const int g    = lane >> 2;
    const int t    = lane & 3;
    const int wm   = (wid >> 2) * 32;
    const int wn   = (wid & 3) * 32;

    const int m0 = blockIdx.x * 128;
    const int n0 = blockIdx.y * 128;
    const int b  = blockIdx.z;
    const float* inb  = in  + (size_t)b * ELEMS_PER_IMG;
    float*       outb = out + (size_t)b * ELEMS_PER_IMG;

    const int fa0 = tid, fa1 = tid + 512;
    const int fb0 = tid, fb1 = tid + 512;

    float acc[2][4][4];
#pragma unroll
    for (int i = 0; i < 2; i++)
#pragma unroll
        for (int j = 0; j < 4; j++)
#pragma unroll
            for (int e = 0; e < 4; e++) acc[i][j][e] = 0.0f;

    float4 sA0, sA1, sB0, sB1;
    sA0 = *reinterpret_cast<const float4*>(&Wmat[(m0 + (fa0 >> 3)) * CC + (fa0 & 7) * 4]);
    sA1 = *reinterpret_cast<const float4*>(&Wmat[(m0 + (fa1 >> 3)) * CC + (fa1 & 7) * 4]);
    sB0 = *reinterpret_cast<const float4*>(&inb[(size_t)(fb0 >> 5) * HWSZ + n0 + (fb0 & 31) * 4]);
    sB1 = *reinterpret_cast<const float4*>(&inb[(size_t)(fb1 >> 5) * HWSZ + n0 + (fb1 & 31) * 4]);
    {
        uint32_t* Ad = Abuf[0];
        uint32_t* Bd = Bbuf[0];
        Ad[(fa0 >> 3) * PA + (fa0 & 7) * 4 + 0] = f2tf32(sA0.x);
        Ad[(fa0 >> 3) * PA + (fa0 & 7) * 4 + 1] = f2tf32(sA0.y);
        Ad[(fa0 >> 3) * PA + (fa0 & 7) * 4 + 2] = f2tf32(sA0.z);
        Ad[(fa0 >> 3) * PA + (fa0 & 7) * 4 + 3] = f2tf32(sA0.w);
        Ad[(fa1 >> 3) * PA + (fa1 & 7) * 4 + 0] = f2tf32(sA1.x);
        Ad[(fa1 >> 3) * PA + (fa1 & 7) * 4 + 1] = f2tf32(sA1.y);
        Ad[(fa1 >> 3) * PA + (fa1 & 7) * 4 + 2] = f2tf32(sA1.z);
        Ad[(fa1 >> 3) * PA + (fa1 & 7) * 4 + 3] = f2tf32(sA1.w);
        Bd[(fb0 >> 5) * PB + (fb0 & 31) * 4 + 0] = f2tf32(sB0.x);
        Bd[(fb0 >> 5) * PB + (fb0 & 31) * 4 + 1] = f2tf32(sB0.y);
        Bd[(fb0 >> 5) * PB + (fb0 & 31) * 4 + 2] = f2tf32(sB0.z);
        Bd[(fb0 >> 5) * PB + (fb0 & 31) * 4 + 3] = f2tf32(sB0.w);
        Bd[(fb1 >> 5) * PB + (fb1 & 31) * 4 + 0] = f2tf32(sB1.x);
        Bd[(fb1 >> 5) * PB + (fb1 & 31) * 4 + 1] = f2tf32(sB1.y);
        Bd[(fb1 >> 5) * PB + (fb1 & 31) * 4 + 2] = f2tf32(sB1.z);
        Bd[(fb1 >> 5) * PB + (fb1 & 31) * 4 + 3] = f2tf32(sB1.w);
    }
    __syncthreads();

    for (int i = 0; i < 8; ++i) {
        const int p = i & 1;

        if (i < 7) {
            const int kk2 = (i + 1) * 32;
            sA0 = *reinterpret_cast<const float4*>(&Wmat[(m0 + (fa0 >> 3)) * CC + kk2 + (fa0 & 7) * 4]);
            sA1 = *reinterpret_cast<const float4*>(&Wmat[(m0 + (fa1 >> 3)) * CC + kk2 + (fa1 & 7) * 4]);
            sB0 = *reinterpret_cast<const float4*>(&inb[(size_t)(kk2 + (fb0 >> 5)) * HWSZ + n0 + (fb0 & 31) * 4]);
            sB1 = *reinterpret_cast<const float4*>(&inb[(size_t)(kk2 + (fb1 >> 5)) * HWSZ + n0 + (fb1 & 31) * 4]);
        }

        const uint32_t* As = Abuf[p];
        const uint32_t* Bs = Bbuf[p];
#pragma unroll
        for (int ks = 0; ks < 4; ++ks) {
            uint32_t afr[2][4], bfr[4][2];
#pragma unroll
            for (int f = 0; f < 2; ++f) {
                const int row = wm + f * 16 + g;
                afr[f][0] = As[row * PA + ks * 8 + t];
                afr[f][1] = As[(row + 8) * PA + ks * 8 + t];
                afr[f][2] = As[row * PA + ks * 8 + t + 4];
                afr[f][3] = As[(row + 8) * PA + ks * 8 + t + 4];
            }
#pragma unroll
            for (int j = 0; j < 4; ++j) {
                const int col = wn + j * 8 + g;
                bfr[j][0] = Bs[(ks * 8 + t) * PB + col];
                bfr[j][1] = Bs[(ks * 8 + t + 4) * PB + col];
            }
#pragma unroll
            for (int f = 0; f < 2; ++f)
#pragma unroll
                for (int j = 0; j < 4; ++j)
                    mma_tf32(acc[f][j], afr[f], bfr[j]);
        }

        if (i < 7) {
            uint32_t* Ad = Abuf[p ^ 1];
            uint32_t* Bd = Bbuf[p ^ 1];
            Ad[(fa0 >> 3) * PA + (fa0 & 7) * 4 + 0] = f2tf32(sA0.x);
            Ad[(fa0 >> 3) * PA + (fa0 & 7) * 4 + 1] = f2tf32(sA0.y);
            Ad[(fa0 >> 3) * PA + (fa0 & 7) * 4 + 2] = f2tf32(sA0.z);
            Ad[(fa0 >> 3) * PA + (fa0 & 7) * 4 + 3] = f2tf32(sA0.w);
            Ad[(fa1 >> 3) * PA + (fa1 & 7) * 4 + 0] = f2tf32(sA1.x);
            Ad[(fa1 >> 3) * PA + (fa1 & 7) * 4 + 1] = f2tf32(sA1.y);
            Ad[(fa1 >> 3) * PA + (fa1 & 7) * 4 + 2] = f2tf32(sA1.z);
            Ad[(fa1 >> 3) * PA + (fa1 & 7) * 4 + 3] = f2tf32(sA1.w);
            Bd[(fb0 >> 5) * PB + (fb0 & 31) * 4 + 0] = f2tf32(sB0.x);
            Bd[(fb0 >> 5) * PB + (fb0 & 31) * 4 + 1] = f2tf32(sB0.y);
            Bd[(fb0 >> 5) * PB + (fb0 & 31) * 4 + 2] = f2tf32(sB0.z);
            Bd[(fb0 >> 5) * PB + (fb0 & 31) * 4 + 3] = f2tf32(sB0.w);
            Bd[(fb1 >> 5) * PB + (fb1 & 31) * 4 + 0] = f2tf32(sB1.x);
            Bd[(fb1 >> 5) * PB + (fb1 & 31) * 4 + 1] = f2tf32(sB1.y);
            Bd[(fb1 >> 5) * PB + (fb1 & 31) * 4 + 2] = f2tf32(sB1.z);
            Bd[(fb1 >> 5) * PB + (fb1 & 31) * 4 + 3] = f2tf32(sB1.w);
        }
        __syncthreads();
    }

    const float* resb = res ? res + (size_t)b * ELEMS_PER_IMG : nullptr;
#pragma unroll
    for (int f = 0; f < 2; ++f) {
#pragma unroll
        for (int j = 0; j < 4; ++j) {
            const int row = m0 + wm + f * 16 + g;
            const int col = n0 + wn + j * 8 + 2 * t;
            float2 v0 = { acc[f][j][0], acc[f][j][1] };
            float2 v1 = { acc[f][j][2], acc[f][j][3] };
            if (do_relu) {
                float2 r0 = *reinterpret_cast<const float2*>(&resb[(size_t)row * HWSZ + col]);
                float2 r1 = *reinterpret_cast<const float2*>(&resb[(size_t)(row + 8) * HWSZ + col]);
                v0.x = fmaxf(v0.x + r0.x, 0.0f);
                v0.y = fmaxf(v0.y + r0.y, 0.0f);
                v1.x = fmaxf(v1.x + r1.x, 0.0f);
                v1.y = fmaxf(v1.y + r1.y, 0.0f);
            }
            *reinterpret_cast<float2*>(&outb[(size_t)row * HWSZ + col]) = v0;
            *reinterpret_cast<float2*>(&outb[(size_t)(row + 8) * HWSZ + col]) = v1;
        }
    }
}

// ============================================================================
// Tensor-core attention per (b,c): S = Q@K (tf32 MMA) -> softmax -> Z = M@V.
// 224 threads = 7 warps; warp w owns rows 16w..16w+15 (7*16 = 112 exact).
// Per warp: 14 n-frags x 14 k-steps of m16n8k8.
// smem: Ks/Vs [k][j] tf32 pitch 120 (conflict-free B-frag loads);
//       Ms holds Q (A operand), then is overwritten with M (warp-private rows).
// ============================================================================
#define PT 120
#define ATTN_SMEM (3 * HH * PT * 4)     // 161,280 B

__global__ void __launch_bounds__(224, 1)
attn_tc_kernel(const float* __restrict__ Q, const float* __restrict__ K,
               const float* __restrict__ V, float* __restrict__ Z)
{
    extern __shared__ uint32_t smu[];
    uint32_t* Ks = smu;                  // K[k][j] tf32
    uint32_t* Vs = smu + HH * PT;        // V[k][j] tf32
    uint32_t* Ms = smu + 2 * HH * PT;    // Q[row][k] tf32, later M[row][k]

    const size_t base = (size_t)blockIdx.x * HWSZ;
    const int tid  = threadIdx.x;
    const int wid  = tid >> 5;           // 0..6
    const int lane = tid & 31;
    const int g    = lane >> 2;          // 0..7
    const int t    = lane & 3;           // 0..3
    const int r0   = wid * 16;

    // ---- stage Q,K,V into smem as tf32 (3136 float4 each, 14 iters) ----
    {
        const float4* Qg = reinterpret_cast<const float4*>(Q + base);
        const float4* Kg = reinterpret_cast<const float4*>(K + base);
        const float4* Vg = reinterpret_cast<const float4*>(V + base);
        for (int i = tid; i < HWSZ / 4; i += 224) {
            const int row = i / 28;
            const int c4  = (i % 28) * 4;
            float4 q = Qg[i], k = Kg[i], v = Vg[i];
            uint32_t* md = &Ms[row * PT + c4];
            md[0] = f2tf32(q.x); md[1] = f2tf32(q.y);
            md[2] = f2tf32(q.z); md[3] = f2tf32(q.w);
            uint32_t* kd = &Ks[row * PT + c4];
            kd[0] = f2tf32(k.x); kd[1] = f2tf32(k.y);
            kd[2] = f2tf32(k.z); kd[3] = f2tf32(k.w);
            uint32_t* vd = &Vs[row * PT + c4];
            vd[0] = f2tf32(v.x); vd[1] = f2tf32(v.y);
            vd[2] = f2tf32(v.z); vd[3] = f2tf32(v.w);
        }
    }
    __syncthreads();

    float acc[14][4];
#pragma unroll
    for (int j = 0; j < 14; j++)
#pragma unroll
        for (int e = 0; e < 4; e++) acc[j][e] = 0.0f;

    // ---- S = Q @ K ----
#pragma unroll 2
    for (int ks = 0; ks < 14; ++ks) {
        uint32_t a[4];
        a[0] = Ms[(r0 + g)     * PT + ks * 8 + t];
        a[1] = Ms[(r0 + g + 8) * PT + ks * 8 + t];
        a[2] = Ms[(r0 + g)     * PT + ks * 8 + t + 4];
        a[3] = Ms[(r0 + g + 8) * PT + ks * 8 + t + 4];
#pragma unroll
        for (int j = 0; j < 14; ++j) {
            uint32_t b[2];
            b[0] = Ks[(ks * 8 + t)     * PT + j * 8 + g];
            b[1] = Ks[(ks * 8 + t + 4) * PT + j * 8 + g];
            mma_tf32(acc[j], a, b);
        }
    }

    // ---- softmax over rows g (c0,c1) and g+8 (c2,c3); quad = lanes same g ----
    {
        float mx0 = -1e30f, mx1 = -1e30f;
#pragma unroll
        for (int j = 0; j < 14; ++j) {
            mx0 = fmaxf(mx0, fmaxf(acc[j][0], acc[j][1]));
            mx1 = fmaxf(mx1, fmaxf(acc[j][2], acc[j][3]));
        }
        mx0 = fmaxf(mx0, __shfl_xor_sync(0xffffffffu, mx0, 1));
        mx0 = fmaxf(mx0, __shfl_xor_sync(0xffffffffu, mx0, 2));
        mx1 = fmaxf(mx1, __shfl_xor_sync(0xffffffffu, mx1, 1));
        mx1 = fmaxf(mx1, __shfl_xor_sync(0xffffffffu, mx1, 2));
        float s0 = 0.0f, s1 = 0.0f;
#pragma unroll
        for (int j = 0; j < 14; ++j) {
            acc[j][0] = __expf(acc[j][0] - mx0);
            acc[j][1] = __expf(acc[j][1] - mx0);
            acc[j][2] = __expf(acc[j][2] - mx1);
            acc[j][3] = __expf(acc[j][3] - mx1);
            s0 += acc[j][0] + acc[j][1];
            s1 += acc[j][2] + acc[j][3];
        }
        s0 += __shfl_xor_sync(0xffffffffu, s0, 1);
        s0 += __shfl_xor_sync(0xffffffffu, s0, 2);
        s1 += __shfl_xor_sync(0xffffffffu, s1, 1);
        s1 += __shfl_xor_sync(0xffffffffu, s1, 2);
        const float i0 = 1.0f / s0, i1 = 1.0f / s1;
#pragma unroll
        for (int j = 0; j < 14; ++j) {
            acc[j][0] *= i0; acc[j][1] *= i0;
            acc[j][2] *= i1; acc[j][3] *= i1;
        }
    }

    // ---- write M into Ms (warp-private rows; Q frags already consumed) ----
    __syncwarp();
#pragma unroll
    for (int j = 0; j < 14; ++j) {
        const int c = j * 8 + 2 * t;
        Ms[(r0 + g)     * PT + c]     = f2tf32(acc[j][0]);
        Ms[(r0 + g)     * PT + c + 1] = f2tf32(acc[j][1]);
        Ms[(r0 + g + 8) * PT + c]     = f2tf32(acc[j][2]);
        Ms[(r0 + g + 8) * PT + c + 1] = f2tf32(acc[j][3]);
    }
    __syncwarp();

    // ---- Z = M @ V (reuse acc) ----
#pragma unroll
    for (int j = 0; j < 14; j++)
#pragma unroll
        for (int e = 0; e < 4; e++) acc[j][e] = 0.0f;

#pragma unroll 2
    for (int ks = 0; ks < 14; ++ks) {
        uint32_t a[4];
        a[0] = Ms[(r0 + g)     * PT + ks * 8 + t];
        a[1] = Ms[(r0 + g + 8) * PT + ks * 8 + t];
        a[2] = Ms[(r0 + g)     * PT + ks * 8 + t + 4];
        a[3] = Ms[(r0 + g + 8) * PT + ks * 8 + t + 4];
#pragma unroll
        for (int j = 0; j < 14; ++j) {
            uint32_t b[2];
            b[0] = Vs[(ks * 8 + t)     * PT + j * 8 + g];
            b[1] = Vs[(ks * 8 + t + 4) * PT + j * 8 + g];
            mma_tf32(acc[j], a, b);
        }
    }

    // ---- store Z from C frags (float2, 8B-aligned) ----
    float* Zb = Z + base;
#pragma unroll
    for (int j = 0; j < 14; ++j) {
        const int col = j * 8 + 2 * t;
        float2 v0 = { acc[j][0], acc[j][1] };
        float2 v1 = { acc[j][2], acc[j][3] };
        *reinterpret_cast<float2*>(&Zb[(r0 + g)     * HH + col]) = v0;
        *reinterpret_cast<float2*>(&Zb[(r0 + g + 8) * HH + col]) = v1;
    }
}

extern "C" void kernel_launch(void* const* d_in, const int* in_sizes, int n_in,
                              void* d_out, int out_size)
{
    const float* x  = (const float*)d_in[0];
    const float* y  = (const float*)d_in[1];
    const float* WQ = (const float*)d_in[2];
    const float* WK = (const float*)d_in[3];
    const float* WV = (const float*)d_in[4];
    const float* WZ = (const float*)d_in[5];
    float* out = (float*)d_out;

    float *dQ, *dK, *dV, *dZ;
    cudaGetSymbolAddress((void**)&dQ, g_Q);
    cudaGetSymbolAddress((void**)&dK, g_K);
    cudaGetSymbolAddress((void**)&dV, g_V);
    cudaGetSymbolAddress((void**)&dZ, g_Zs);

    cudaFuncSetAttribute(attn_tc_kernel, cudaFuncAttributeMaxDynamicSharedMemorySize,
                         ATTN_SMEM);
    cudaFuncSetAttribute(gemm_tc_kernel, cudaFuncAttributeMaxDynamicSharedMemorySize,
                         GEMM_SMEM);

    dim3 gg(2, HWSZ / 128, BB);   // m-tile fastest -> B-tile L2 reuse

    gemm_tc_kernel<<<gg, 512, GEMM_SMEM>>>(WQ, x, nullptr, dQ, 0);
    gemm_tc_kernel<<<gg, 512, GEMM_SMEM>>>(WK, y, nullptr, dK, 0);
    gemm_tc_kernel<<<gg, 512, GEMM_SMEM>>>(WV, y, nullptr, dV, 0);
    attn_tc_kernel<<<BB * CC, 224, ATTN_SMEM>>>(dQ, dK, dV, dZ);
    gemm_tc_kernel<<<gg, 512, GEMM_SMEM>>>(WZ, dZ, x, out, 1);
}

// round 9
// speedup vs baseline: 2.1141x; 1.2179x over previous
#include <cuda_runtime.h>
#include <cuda_bf16.h>
#include <cstdint>

// Problem constants
#define BB 8
#define CC 256
#define HH 112
#define HWSZ 12544              // 112*112
#define ELEMS_PER_IMG (CC * HWSZ)
#define TOTAL_ELEMS (BB * ELEMS_PER_IMG)

// Scratch (device globals; no allocations allowed)
__device__ float g_Q[TOTAL_ELEMS];
__device__ float g_K[TOTAL_ELEMS];
__device__ float g_V[TOTAL_ELEMS];
__device__ float g_Zs[TOTAL_ELEMS];

__device__ __forceinline__ uint32_t f2tf32(float f) {
    uint32_t r;
    asm("cvt.rna.tf32.f32 %0, %1;" : "=r"(r) : "f"(f));
    return r;
}
// pack two floats into bf16x2: lo -> low half, hi -> high half
__device__ __forceinline__ uint32_t pack_bf16(float lo, float hi) {
    uint32_t r;
    asm("cvt.rn.bf16x2.f32 %0, %1, %2;" : "=r"(r) : "f"(hi), "f"(lo));
    return r;
}

// mma.sync m16n8k8 tf32 (baseline PTX; used by attention)
__device__ __forceinline__ void mma_tf32(float* c, const uint32_t* a, const uint32_t* b) {
    asm volatile(
        "mma.sync.aligned.m16n8k8.row.col.f32.tf32.tf32.f32 "
        "{%0,%1,%2,%3}, {%4,%5,%6,%7}, {%8,%9}, {%0,%1,%2,%3};"
        : "+f"(c[0]), "+f"(c[1]), "+f"(c[2]), "+f"(c[3])
        : "r"(a[0]), "r"(a[1]), "r"(a[2]), "r"(a[3]), "r"(b[0]), "r"(b[1]));
}

// mma.sync m16n8k16 bf16 (baseline PTX; used by the 1x1-conv GEMMs)
__device__ __forceinline__ void mma_bf16(float* c, const uint32_t* a, const uint32_t* b) {
    asm volatile(
        "mma.sync.aligned.m16n8k16.row.col.f32.bf16.bf16.f32 "
        "{%0,%1,%2,%3}, {%4,%5,%6,%7}, {%8,%9}, {%0,%1,%2,%3};"
        : "+f"(c[0]), "+f"(c[1]), "+f"(c[2]), "+f"(c[3])
        : "r"(a[0]), "r"(a[1]), "r"(a[2]), "r"(a[3]), "r"(b[0]), "r"(b[1]));
}

// ============================================================================
// bf16 tensor-core GEMM: out[b,o,s] = sum_c W[o,c] * in[b,c,s] (+res+relu)
// CTA: 512 threads (16 warps 4x4), tile M=128, N=128, K=256 (8 chunks of 32).
// Both operands stored in smem as bf16x2 words, [row][16 slots], pitch 36,
// k-pair interleaved (pos 2u -> kp u, pos 2u+1 -> kp u+4 within each k16 grp)
// so every MMA fragment is a single LDS.64. B transposed in-flight to [n][kp].
// Warp tile 32x32: 2 m-frags x 4 n-frags, 8 MMAs per k16 step.
// ============================================================================
#define PAB 36
#define TILE_B32 (128 * PAB)                 // 4608 words = 18432 B
#define GEMM_SMEM (4 * TILE_B32 * 4)         // A0,B0,A1,B1 = 73728 B

__global__ void __launch_bounds__(512, 1)
gemm_tc_kernel(const float* __restrict__ Wmat,
               const float* __restrict__ in,
               const float* __restrict__ res,
               float* __restrict__ out,
               int do_relu)
{
    extern __shared__ uint32_t smu[];
    // layout: [A stage0][B stage0][A stage1][B stage1]
    uint32_t* Abuf[2] = { smu,                smu + 2 * TILE_B32 };
    uint32_t* Bbuf[2] = { smu + TILE_B32,     smu + 3 * TILE_B32 };

    const int tid  = threadIdx.x;
    const int wid  = tid >> 5;
    const int lane = tid & 31;
    const int g    = lane >> 2;
    const int t    = lane & 3;
    const int wm   = (wid >> 2) * 32;
    const int wn   = (wid & 3) * 32;

    const int m0 = blockIdx.x * 128;
    const int n0 = blockIdx.y * 128;
    const int b  = blockIdx.z;
    const float* inb  = in  + (size_t)b * ELEMS_PER_IMG;
    float*       outb = out + (size_t)b * ELEMS_PER_IMG;

    // staging map: q selects slot quad (0..3), r = row (m for A, n for B)
    const int q   = tid >> 7;            // 0..3
    const int rr  = tid & 127;           // 0..127
    // source k base within chunk for this quad:
    //   quad q covers slots q*4..q*4+3 = k16-group (q>>1), k offset (q&1)*4
    // needed k values: base+0..3 (kp lo pair) and base+8..11 (kp hi pair)
    const int kbase = (q >> 1) * 16 + (q & 1) * 4;
    const int sts_off = rr * PAB + q * 4;

    float acc[2][4][4];
#pragma unroll
    for (int i = 0; i < 2; i++)
#pragma unroll
        for (int j = 0; j < 4; j++)
#pragma unroll
            for (int e = 0; e < 4; e++) acc[i][j][e] = 0.0f;

    // ---- prologue: stage chunk 0 ----
    float4 av0, av1;
    float  bv[8];
    {
        const float* arow = &Wmat[(m0 + rr) * CC + kbase];
        av0 = *reinterpret_cast<const float4*>(arow);
        av1 = *reinterpret_cast<const float4*>(arow + 8);
        const float* bcol = &inb[(size_t)kbase * HWSZ + n0 + rr];
#pragma unroll
        for (int e = 0; e < 4; ++e) {
            bv[e]     = bcol[(size_t)e * HWSZ];
            bv[e + 4] = bcol[(size_t)(e + 8) * HWSZ];
        }
        uint4 qa = { pack_bf16(av0.x, av0.y), pack_bf16(av1.x, av1.y),
                     pack_bf16(av0.z, av0.w), pack_bf16(av1.z, av1.w) };
        *reinterpret_cast<uint4*>(&Abuf[0][sts_off]) = qa;
        uint4 qb = { pack_bf16(bv[0], bv[1]), pack_bf16(bv[4], bv[5]),
                     pack_bf16(bv[2], bv[3]), pack_bf16(bv[6], bv[7]) };
        *reinterpret_cast<uint4*>(&Bbuf[0][sts_off]) = qb;
    }
    __syncthreads();

    for (int i = 0; i < 8; ++i) {
        const int p = i & 1;

        // prefetch next chunk (global -> regs)
        if (i < 7) {
            const int kk2 = (i + 1) * 32 + kbase;
            const float* arow = &Wmat[(m0 + rr) * CC + kk2];
            av0 = *reinterpret_cast<const float4*>(arow);
            av1 = *reinterpret_cast<const float4*>(arow + 8);
            const float* bcol = &inb[(size_t)kk2 * HWSZ + n0 + rr];
#pragma unroll
            for (int e = 0; e < 4; ++e) {
                bv[e]     = bcol[(size_t)e * HWSZ];
                bv[e + 4] = bcol[(size_t)(e + 8) * HWSZ];
            }
        }

        // compute chunk i: 2 k16 steps, all-LDS.64 fragment loads
        const uint32_t* As = Abuf[p];
        const uint32_t* Bs = Bbuf[p];
#pragma unroll
        for (int ks = 0; ks < 2; ++ks) {
            const int so = ks * 8 + 2 * t;
            uint32_t afr[2][4];
#pragma unroll
            for (int f = 0; f < 2; ++f) {
                const int row = wm + f * 16 + g;
                uint2 lo = *reinterpret_cast<const uint2*>(&As[row * PAB + so]);
                uint2 hi = *reinterpret_cast<const uint2*>(&As[(row + 8) * PAB + so]);
                afr[f][0] = lo.x; afr[f][1] = hi.x;
                afr[f][2] = lo.y; afr[f][3] = hi.y;
            }
#pragma unroll
            for (int j = 0; j < 4; ++j) {
                const int col = wn + j * 8 + g;
                uint2 bb = *reinterpret_cast<const uint2*>(&Bs[col * PAB + so]);
                uint32_t bfr[2] = { bb.x, bb.y };
#pragma unroll
                for (int f = 0; f < 2; ++f)
                    mma_bf16(acc[f][j], afr[f], bfr);
            }
        }

        // store prefetched chunk into the other buffers
        if (i < 7) {
            uint4 qa = { pack_bf16(av0.x, av0.y), pack_bf16(av1.x, av1.y),
                         pack_bf16(av0.z, av0.w), pack_bf16(av1.z, av1.w) };
            *reinterpret_cast<uint4*>(&Abuf[p ^ 1][sts_off]) = qa;
            uint4 qb = { pack_bf16(bv[0], bv[1]), pack_bf16(bv[4], bv[5]),
                         pack_bf16(bv[2], bv[3]), pack_bf16(bv[6], bv[7]) };
            *reinterpret_cast<uint4*>(&Bbuf[p ^ 1][sts_off]) = qb;
        }
        __syncthreads();
    }

    // ---- epilogue: C frags -> global (float2), fused residual+relu ----
    const float* resb = res ? res + (size_t)b * ELEMS_PER_IMG : nullptr;
#pragma unroll
    for (int f = 0; f < 2; ++f) {
#pragma unroll
        for (int j = 0; j < 4; ++j) {
            const int row = m0 + wm + f * 16 + g;
            const int col = n0 + wn + j * 8 + 2 * t;
            float2 v0 = { acc[f][j][0], acc[f][j][1] };
            float2 v1 = { acc[f][j][2], acc[f][j][3] };
            if (do_relu) {
                float2 r0 = *reinterpret_cast<const float2*>(&resb[(size_t)row * HWSZ + col]);
                float2 r1 = *reinterpret_cast<const float2*>(&resb[(size_t)(row + 8) * HWSZ + col]);
                v0.x = fmaxf(v0.x + r0.x, 0.0f);
                v0.y = fmaxf(v0.y + r0.y, 0.0f);
                v1.x = fmaxf(v1.x + r1.x, 0.0f);
                v1.y = fmaxf(v1.y + r1.y, 0.0f);
            }
            *reinterpret_cast<float2*>(&outb[(size_t)row * HWSZ + col]) = v0;
            *reinterpret_cast<float2*>(&outb[(size_t)(row + 8) * HWSZ + col]) = v1;
        }
    }
}

// ============================================================================
// Tensor-core attention per (b,c) — unchanged from R8 passing version (tf32).
// ============================================================================
#define PT 120
#define ATTN_SMEM (3 * HH * PT * 4)     // 161,280 B

__global__ void __launch_bounds__(224, 1)
attn_tc_kernel(const float* __restrict__ Q, const float* __restrict__ K,
               const float* __restrict__ V, float* __restrict__ Z)
{
    extern __shared__ uint32_t smu[];
    uint32_t* Ks = smu;                  // K[k][j] tf32
    uint32_t* Vs = smu + HH * PT;        // V[k][j] tf32
    uint32_t* Ms = smu + 2 * HH * PT;    // Q[row][k] tf32, later M[row][k]

    const size_t base = (size_t)blockIdx.x * HWSZ;
    const int tid  = threadIdx.x;
    const int wid  = tid >> 5;           // 0..6
    const int lane = tid & 31;
    const int g    = lane >> 2;          // 0..7
    const int t    = lane & 3;           // 0..3
    const int r0   = wid * 16;

    {
        const float4* Qg = reinterpret_cast<const float4*>(Q + base);
        const float4* Kg = reinterpret_cast<const float4*>(K + base);
        const float4* Vg = reinterpret_cast<const float4*>(V + base);
        for (int i = tid; i < HWSZ / 4; i += 224) {
            const int row = i / 28;
            const int c4  = (i % 28) * 4;
            float4 qv = Qg[i], kv = Kg[i], vv = Vg[i];
            uint32_t* md = &Ms[row * PT + c4];
            md[0] = f2tf32(qv.x); md[1] = f2tf32(qv.y);
            md[2] = f2tf32(qv.z); md[3] = f2tf32(qv.w);
            uint32_t* kd = &Ks[row * PT + c4];
            kd[0] = f2tf32(kv.x); kd[1] = f2tf32(kv.y);
            kd[2] = f2tf32(kv.z); kd[3] = f2tf32(kv.w);
            uint32_t* vd = &Vs[row * PT + c4];
            vd[0] = f2tf32(vv.x); vd[1] = f2tf32(vv.y);
            vd[2] = f2tf32(vv.z); vd[3] = f2tf32(vv.w);
        }
    }
    __syncthreads();

    float acc[14][4];
#pragma unroll
    for (int j = 0; j < 14; j++)
#pragma unroll
        for (int e = 0; e < 4; e++) acc[j][e] = 0.0f;

#pragma unroll 2
    for (int ks = 0; ks < 14; ++ks) {
        uint32_t a[4];
        a[0] = Ms[(r0 + g)     * PT + ks * 8 + t];
        a[1] = Ms[(r0 + g + 8) * PT + ks * 8 + t];
        a[2] = Ms[(r0 + g)     * PT + ks * 8 + t + 4];
        a[3] = Ms[(r0 + g + 8) * PT + ks * 8 + t + 4];
#pragma unroll
        for (int j = 0; j < 14; ++j) {
            uint32_t bfr[2];
            bfr[0] = Ks[(ks * 8 + t)     * PT + j * 8 + g];
            bfr[1] = Ks[(ks * 8 + t + 4) * PT + j * 8 + g];
            mma_tf32(acc[j], a, bfr);
        }
    }

    {
        float mx0 = -1e30f, mx1 = -1e30f;
#pragma unroll
        for (int j = 0; j < 14; ++j) {
            mx0 = fmaxf(mx0, fmaxf(acc[j][0], acc[j][1]));
            mx1 = fmaxf(mx1, fmaxf(acc[j][2], acc[j][3]));
        }
        mx0 = fmaxf(mx0, __shfl_xor_sync(0xffffffffu, mx0, 1));
        mx0 = fmaxf(mx0, __shfl_xor_sync(0xffffffffu, mx0, 2));
        mx1 = fmaxf(mx1, __shfl_xor_sync(0xffffffffu, mx1, 1));
        mx1 = fmaxf(mx1, __shfl_xor_sync(0xffffffffu, mx1, 2));
        float s0 = 0.0f, s1 = 0.0f;
#pragma unroll
        for (int j = 0; j < 14; ++j) {
            acc[j][0] = __expf(acc[j][0] - mx0);
            acc[j][1] = __expf(acc[j][1] - mx0);
            acc[j][2] = __expf(acc[j][2] - mx1);
            acc[j][3] = __expf(acc[j][3] - mx1);
            s0 += acc[j][0] + acc[j][1];
            s1 += acc[j][2] + acc[j][3];
        }
        s0 += __shfl_xor_sync(0xffffffffu, s0, 1);
        s0 += __shfl_xor_sync(0xffffffffu, s0, 2);
        s1 += __shfl_xor_sync(0xffffffffu, s1, 1);
        s1 += __shfl_xor_sync(0xffffffffu, s1, 2);
        const float i0 = 1.0f / s0, i1 = 1.0f / s1;
#pragma unroll
        for (int j = 0; j < 14; ++j) {
            acc[j][0] *= i0; acc[j][1] *= i0;
            acc[j][2] *= i1; acc[j][3] *= i1;
        }
    }

    __syncwarp();
#pragma unroll
    for (int j = 0; j < 14; ++j) {
        const int c = j * 8 + 2 * t;
        Ms[(r0 + g)     * PT + c]     = f2tf32(acc[j][0]);
        Ms[(r0 + g)     * PT + c + 1] = f2tf32(acc[j][1]);
        Ms[(r0 + g + 8) * PT + c]     = f2tf32(acc[j][2]);
        Ms[(r0 + g + 8) * PT + c + 1] = f2tf32(acc[j][3]);
    }
    __syncwarp();

#pragma unroll
    for (int j = 0; j < 14; j++)
#pragma unroll
        for (int e = 0; e < 4; e++) acc[j][e] = 0.0f;

#pragma unroll 2
    for (int ks = 0; ks < 14; ++ks) {
        uint32_t a[4];
        a[0] = Ms[(r0 + g)     * PT + ks * 8 + t];
        a[1] = Ms[(r0 + g + 8) * PT + ks * 8 + t];
        a[2] = Ms[(r0 + g)     * PT + ks * 8 + t + 4];
        a[3] = Ms[(r0 + g + 8) * PT + ks * 8 + t + 4];
#pragma unroll
        for (int j = 0; j < 14; ++j) {
            uint32_t bfr[2];
            bfr[0] = Vs[(ks * 8 + t)     * PT + j * 8 + g];
            bfr[1] = Vs[(ks * 8 + t + 4) * PT + j * 8 + g];
            mma_tf32(acc[j], a, bfr);
        }
    }

    float* Zb = Z + base;
#pragma unroll
    for (int j = 0; j < 14; ++j) {
        const int col = j * 8 + 2 * t;
        float2 v0 = { acc[j][0], acc[j][1] };
        float2 v1 = { acc[j][2], acc[j][3] };
        *reinterpret_cast<float2*>(&Zb[(r0 + g)     * HH + col]) = v0;
        *reinterpret_cast<float2*>(&Zb[(r0 + g + 8) * HH + col]) = v1;
    }
}

extern "C" void kernel_launch(void* const* d_in, const int* in_sizes, int n_in,
                              void* d_out, int out_size)
{
    const float* x  = (const float*)d_in[0];
    const float* y  = (const float*)d_in[1];
    const float* WQ = (const float*)d_in[2];
    const float* WK = (const float*)d_in[3];
    const float* WV = (const float*)d_in[4];
    const float* WZ = (const float*)d_in[5];
    float* out = (float*)d_out;

    float *dQ, *dK, *dV, *dZ;
    cudaGetSymbolAddress((void**)&dQ, g_Q);
    cudaGetSymbolAddress((void**)&dK, g_K);
    cudaGetSymbolAddress((void**)&dV, g_V);
    cudaGetSymbolAddress((void**)&dZ, g_Zs);

    cudaFuncSetAttribute(attn_tc_kernel, cudaFuncAttributeMaxDynamicSharedMemorySize,
                         ATTN_SMEM);
    cudaFuncSetAttribute(gemm_tc_kernel, cudaFuncAttributeMaxDynamicSharedMemorySize,
                         GEMM_SMEM);

    dim3 gg(2, HWSZ / 128, BB);   // m-tile fastest -> B-tile L2 reuse

    gemm_tc_kernel<<<gg, 512, GEMM_SMEM>>>(WQ, x, nullptr, dQ, 0);
    gemm_tc_kernel<<<gg, 512, GEMM_SMEM>>>(WK, y, nullptr, dK, 0);
    gemm_tc_kernel<<<gg, 512, GEMM_SMEM>>>(WV, y, nullptr, dV, 0);
    attn_tc_kernel<<<BB * CC, 224, ATTN_SMEM>>>(dQ, dK, dV, dZ);
    gemm_tc_kernel<<<gg, 512, GEMM_SMEM>>>(WZ, dZ, x, out, 1);
}

// round 10
// speedup vs baseline: 2.2416x; 1.0603x over previous
#include <cuda_runtime.h>
#include <cuda_bf16.h>
#include <cstdint>

// Problem constants
#define BB 8
#define CC 256
#define HH 112
#define HWSZ 12544              // 112*112
#define ELEMS_PER_IMG (CC * HWSZ)
#define TOTAL_ELEMS (BB * ELEMS_PER_IMG)

// Scratch (device globals; no allocations allowed)
__device__ __nv_bfloat16 g_Q[TOTAL_ELEMS];   // bf16, k-pair words in [row][col] order
__device__ __nv_bfloat16 g_K[TOTAL_ELEMS];
__device__ __nv_bfloat16 g_V[TOTAL_ELEMS];
__device__ float         g_Zs[TOTAL_ELEMS];  // attention output (float)

// pack two floats into bf16x2: lo -> low half, hi -> high half
__device__ __forceinline__ uint32_t pack_bf16(float lo, float hi) {
    uint32_t r;
    asm("cvt.rn.bf16x2.f32 %0, %1, %2;" : "=r"(r) : "f"(hi), "f"(lo));
    return r;
}
__device__ __forceinline__ uint32_t prmt(uint32_t a, uint32_t b, uint32_t sel) {
    uint32_t r;
    asm("prmt.b32 %0, %1, %2, %3;" : "=r"(r) : "r"(a), "r"(b), "r"(sel));
    return r;
}

// mma.sync m16n8k16 bf16 (baseline PTX; fragment layout validated R9)
__device__ __forceinline__ void mma_bf16(float* c, const uint32_t* a, const uint32_t* b) {
    asm volatile(
        "mma.sync.aligned.m16n8k16.row.col.f32.bf16.bf16.f32 "
        "{%0,%1,%2,%3}, {%4,%5,%6,%7}, {%8,%9}, {%0,%1,%2,%3};"
        : "+f"(c[0]), "+f"(c[1]), "+f"(c[2]), "+f"(c[3])
        : "r"(a[0]), "r"(a[1]), "r"(a[2]), "r"(a[3]), "r"(b[0]), "r"(b[1]));
}

// k-pair interleave slot within 8-word k16 group (validated R9):
// kp = 8*ks + u ; slot = 8*ks + (u<4 ? 2u : 2u-7)
__device__ __forceinline__ int kslot(int kp) {
    const int u = kp & 7;
    return (kp & ~7) + ((u < 4) ? (2 * u) : (2 * u - 7));
}

// ============================================================================
// bf16 tensor-core GEMM (single-W): out = W @ in (+res+relu if float out)
// Identical mainloop to R9 passing version; epilogue supports bf16 output.
// ============================================================================
#define PAB 36
#define TILE_B32 (128 * PAB)
#define GEMM_SMEM (4 * TILE_B32 * 4)         // 73728 B

__global__ void __launch_bounds__(512, 1)
gemm_tc_kernel(const float* __restrict__ Wmat,
               const float* __restrict__ in,
               const float* __restrict__ res,
               void* __restrict__ outp,
               int out_bf16, int do_relu)
{
    extern __shared__ uint32_t smu[];
    uint32_t* Abuf[2] = { smu,                smu + 2 * TILE_B32 };
    uint32_t* Bbuf[2] = { smu + TILE_B32,     smu + 3 * TILE_B32 };

    const int tid  = threadIdx.x;
    const int wid  = tid >> 5;
    const int lane = tid & 31;
    const int g    = lane >> 2;
    const int t    = lane & 3;
    const int wm   = (wid >> 2) * 32;
    const int wn   = (wid & 3) * 32;

    const int m0 = blockIdx.x * 128;
    const int n0 = blockIdx.y * 128;
    const int b  = blockIdx.z;
    const float* inb = in + (size_t)b * ELEMS_PER_IMG;

    const int q   = tid >> 7;
    const int rr  = tid & 127;
    const int kbase = (q >> 1) * 16 + (q & 1) * 4;
    const int sts_off = rr * PAB + q * 4;

    float acc[2][4][4];
#pragma unroll
    for (int i = 0; i < 2; i++)
#pragma unroll
        for (int j = 0; j < 4; j++)
#pragma unroll
            for (int e = 0; e < 4; e++) acc[i][j][e] = 0.0f;

    float4 av0, av1;
    float  bv[8];
    {
        const float* arow = &Wmat[(m0 + rr) * CC + kbase];
        av0 = *reinterpret_cast<const float4*>(arow);
        av1 = *reinterpret_cast<const float4*>(arow + 8);
        const float* bcol = &inb[(size_t)kbase * HWSZ + n0 + rr];
#pragma unroll
        for (int e = 0; e < 4; ++e) {
            bv[e]     = bcol[(size_t)e * HWSZ];
            bv[e + 4] = bcol[(size_t)(e + 8) * HWSZ];
        }
        uint4 qa = { pack_bf16(av0.x, av0.y), pack_bf16(av1.x, av1.y),
                     pack_bf16(av0.z, av0.w), pack_bf16(av1.z, av1.w) };
        *reinterpret_cast<uint4*>(&Abuf[0][sts_off]) = qa;
        uint4 qb = { pack_bf16(bv[0], bv[1]), pack_bf16(bv[4], bv[5]),
                     pack_bf16(bv[2], bv[3]), pack_bf16(bv[6], bv[7]) };
        *reinterpret_cast<uint4*>(&Bbuf[0][sts_off]) = qb;
    }
    __syncthreads();

    for (int i = 0; i < 8; ++i) {
        const int p = i & 1;

        if (i < 7) {
            const int kk2 = (i + 1) * 32 + kbase;
            const float* arow = &Wmat[(m0 + rr) * CC + kk2];
            av0 = *reinterpret_cast<const float4*>(arow);
            av1 = *reinterpret_cast<const float4*>(arow + 8);
            const float* bcol = &inb[(size_t)kk2 * HWSZ + n0 + rr];
#pragma unroll
            for (int e = 0; e < 4; ++e) {
                bv[e]     = bcol[(size_t)e * HWSZ];
                bv[e + 4] = bcol[(size_t)(e + 8) * HWSZ];
            }
        }

        const uint32_t* As = Abuf[p];
        const uint32_t* Bs = Bbuf[p];
#pragma unroll
        for (int ks = 0; ks < 2; ++ks) {
            const int so = ks * 8 + 2 * t;
            uint32_t afr[2][4];
#pragma unroll
            for (int f = 0; f < 2; ++f) {
                const int row = wm + f * 16 + g;
                uint2 lo = *reinterpret_cast<const uint2*>(&As[row * PAB + so]);
                uint2 hi = *reinterpret_cast<const uint2*>(&As[(row + 8) * PAB + so]);
                afr[f][0] = lo.x; afr[f][1] = hi.x;
                afr[f][2] = lo.y; afr[f][3] = hi.y;
            }
#pragma unroll
            for (int j = 0; j < 4; ++j) {
                const int col = wn + j * 8 + g;
                uint2 bb = *reinterpret_cast<const uint2*>(&Bs[col * PAB + so]);
                uint32_t bfr[2] = { bb.x, bb.y };
#pragma unroll
                for (int f = 0; f < 2; ++f)
                    mma_bf16(acc[f][j], afr[f], bfr);
            }
        }

        if (i < 7) {
            uint4 qa = { pack_bf16(av0.x, av0.y), pack_bf16(av1.x, av1.y),
                         pack_bf16(av0.z, av0.w), pack_bf16(av1.z, av1.w) };
            *reinterpret_cast<uint4*>(&Abuf[p ^ 1][sts_off]) = qa;
            uint4 qb = { pack_bf16(bv[0], bv[1]), pack_bf16(bv[4], bv[5]),
                         pack_bf16(bv[2], bv[3]), pack_bf16(bv[6], bv[7]) };
            *reinterpret_cast<uint4*>(&Bbuf[p ^ 1][sts_off]) = qb;
        }
        __syncthreads();
    }

    if (out_bf16) {
        uint32_t* ob = reinterpret_cast<uint32_t*>(outp) + (size_t)b * (ELEMS_PER_IMG / 2);
#pragma unroll
        for (int f = 0; f < 2; ++f) {
#pragma unroll
            for (int j = 0; j < 4; ++j) {
                const int row = m0 + wm + f * 16 + g;
                const int col = n0 + wn + j * 8 + 2 * t;   // even
                ob[((size_t)row * HWSZ + col) >> 1]       = pack_bf16(acc[f][j][0], acc[f][j][1]);
                ob[((size_t)(row + 8) * HWSZ + col) >> 1] = pack_bf16(acc[f][j][2], acc[f][j][3]);
            }
        }
    } else {
        float* outb = reinterpret_cast<float*>(outp) + (size_t)b * ELEMS_PER_IMG;
        const float* resb = res ? res + (size_t)b * ELEMS_PER_IMG : nullptr;
#pragma unroll
        for (int f = 0; f < 2; ++f) {
#pragma unroll
            for (int j = 0; j < 4; ++j) {
                const int row = m0 + wm + f * 16 + g;
                const int col = n0 + wn + j * 8 + 2 * t;
                float2 v0 = { acc[f][j][0], acc[f][j][1] };
                float2 v1 = { acc[f][j][2], acc[f][j][3] };
                if (do_relu) {
                    float2 r0 = *reinterpret_cast<const float2*>(&resb[(size_t)row * HWSZ + col]);
                    float2 r1 = *reinterpret_cast<const float2*>(&resb[(size_t)(row + 8) * HWSZ + col]);
                    v0.x = fmaxf(v0.x + r0.x, 0.0f);
                    v0.y = fmaxf(v0.y + r0.y, 0.0f);
                    v1.x = fmaxf(v1.x + r1.x, 0.0f);
                    v1.y = fmaxf(v1.y + r1.y, 0.0f);
                }
                *reinterpret_cast<float2*>(&outb[(size_t)row * HWSZ + col]) = v0;
                *reinterpret_cast<float2*>(&outb[(size_t)(row + 8) * HWSZ + col]) = v1;
            }
        }
    }
}

// ============================================================================
// Fused K+V GEMM: stage the y tile ONCE, run two accumulator sets.
// smem stages: [AK0][AV0][B0][AK1][AV1][B1]
// ============================================================================
#define KV_SMEM (6 * TILE_B32 * 4)           // 110592 B

__global__ void __launch_bounds__(512, 1)
gemm_tc_kv_kernel(const float* __restrict__ WK,
                  const float* __restrict__ WV,
                  const float* __restrict__ in,
                  uint32_t* __restrict__ outK,
                  uint32_t* __restrict__ outV)
{
    extern __shared__ uint32_t smu[];
    uint32_t* AK[2] = { smu,                smu + 3 * TILE_B32 };
    uint32_t* AV[2] = { smu + TILE_B32,     smu + 4 * TILE_B32 };
    uint32_t* BY[2] = { smu + 2 * TILE_B32, smu + 5 * TILE_B32 };

    const int tid  = threadIdx.x;
    const int wid  = tid >> 5;
    const int lane = tid & 31;
    const int g    = lane >> 2;
    const int t    = lane & 3;
    const int wm   = (wid >> 2) * 32;
    const int wn   = (wid & 3) * 32;

    const int m0 = blockIdx.x * 128;
    const int n0 = blockIdx.y * 128;
    const int b  = blockIdx.z;
    const float* inb = in + (size_t)b * ELEMS_PER_IMG;

    const int q   = tid >> 7;
    const int rr  = tid & 127;
    const int kbase = (q >> 1) * 16 + (q & 1) * 4;
    const int sts_off = rr * PAB + q * 4;

    float accK[2][4][4], accV[2][4][4];
#pragma unroll
    for (int i = 0; i < 2; i++)
#pragma unroll
        for (int j = 0; j < 4; j++)
#pragma unroll
            for (int e = 0; e < 4; e++) { accK[i][j][e] = 0.0f; accV[i][j][e] = 0.0f; }

    float4 ak0, ak1, av0, av1;
    float  bv[8];
    {
        const float* krow = &WK[(m0 + rr) * CC + kbase];
        const float* vrow = &WV[(m0 + rr) * CC + kbase];
        ak0 = *reinterpret_cast<const float4*>(krow);
        ak1 = *reinterpret_cast<const float4*>(krow + 8);
        av0 = *reinterpret_cast<const float4*>(vrow);
        av1 = *reinterpret_cast<const float4*>(vrow + 8);
        const float* bcol = &inb[(size_t)kbase * HWSZ + n0 + rr];
#pragma unroll
        for (int e = 0; e < 4; ++e) {
            bv[e]     = bcol[(size_t)e * HWSZ];
            bv[e + 4] = bcol[(size_t)(e + 8) * HWSZ];
        }
        uint4 qk = { pack_bf16(ak0.x, ak0.y), pack_bf16(ak1.x, ak1.y),
                     pack_bf16(ak0.z, ak0.w), pack_bf16(ak1.z, ak1.w) };
        *reinterpret_cast<uint4*>(&AK[0][sts_off]) = qk;
        uint4 qv = { pack_bf16(av0.x, av0.y), pack_bf16(av1.x, av1.y),
                     pack_bf16(av0.z, av0.w), pack_bf16(av1.z, av1.w) };
        *reinterpret_cast<uint4*>(&AV[0][sts_off]) = qv;
        uint4 qb = { pack_bf16(bv[0], bv[1]), pack_bf16(bv[4], bv[5]),
                     pack_bf16(bv[2], bv[3]), pack_bf16(bv[6], bv[7]) };
        *reinterpret_cast<uint4*>(&BY[0][sts_off]) = qb;
    }
    __syncthreads();

    for (int i = 0; i < 8; ++i) {
        const int p = i & 1;

        if (i < 7) {
            const int kk2 = (i + 1) * 32 + kbase;
            const float* krow = &WK[(m0 + rr) * CC + kk2];
            const float* vrow = &WV[(m0 + rr) * CC + kk2];
            ak0 = *reinterpret_cast<const float4*>(krow);
            ak1 = *reinterpret_cast<const float4*>(krow + 8);
            av0 = *reinterpret_cast<const float4*>(vrow);
            av1 = *reinterpret_cast<const float4*>(vrow + 8);
            const float* bcol = &inb[(size_t)kk2 * HWSZ + n0 + rr];
#pragma unroll
            for (int e = 0; e < 4; ++e) {
                bv[e]     = bcol[(size_t)e * HWSZ];
                bv[e + 4] = bcol[(size_t)(e + 8) * HWSZ];
            }
        }

        const uint32_t* Ak = AK[p];
        const uint32_t* Av = AV[p];
        const uint32_t* Bs = BY[p];
#pragma unroll
        for (int ks = 0; ks < 2; ++ks) {
            const int so = ks * 8 + 2 * t;
            uint32_t afk[2][4], afv[2][4];
#pragma unroll
            for (int f = 0; f < 2; ++f) {
                const int row = wm + f * 16 + g;
                uint2 lo = *reinterpret_cast<const uint2*>(&Ak[row * PAB + so]);
                uint2 hi = *reinterpret_cast<const uint2*>(&Ak[(row + 8) * PAB + so]);
                afk[f][0] = lo.x; afk[f][1] = hi.x;
                afk[f][2] = lo.y; afk[f][3] = hi.y;
                uint2 lv = *reinterpret_cast<const uint2*>(&Av[row * PAB + so]);
                uint2 hv = *reinterpret_cast<const uint2*>(&Av[(row + 8) * PAB + so]);
                afv[f][0] = lv.x; afv[f][1] = hv.x;
                afv[f][2] = lv.y; afv[f][3] = hv.y;
            }
#pragma unroll
            for (int j = 0; j < 4; ++j) {
                const int col = wn + j * 8 + g;
                uint2 bb = *reinterpret_cast<const uint2*>(&Bs[col * PAB + so]);
                uint32_t bfr[2] = { bb.x, bb.y };
#pragma unroll
                for (int f = 0; f < 2; ++f) {
                    mma_bf16(accK[f][j], afk[f], bfr);
                    mma_bf16(accV[f][j], afv[f], bfr);
                }
            }
        }

        if (i < 7) {
            uint4 qk = { pack_bf16(ak0.x, ak0.y), pack_bf16(ak1.x, ak1.y),
                         pack_bf16(ak0.z, ak0.w), pack_bf16(ak1.z, ak1.w) };
            *reinterpret_cast<uint4*>(&AK[p ^ 1][sts_off]) = qk;
            uint4 qv = { pack_bf16(av0.x, av0.y), pack_bf16(av1.x, av1.y),
                         pack_bf16(av0.z, av0.w), pack_bf16(av1.z, av1.w) };
            *reinterpret_cast<uint4*>(&AV[p ^ 1][sts_off]) = qv;
            uint4 qb = { pack_bf16(bv[0], bv[1]), pack_bf16(bv[4], bv[5]),
                         pack_bf16(bv[2], bv[3]), pack_bf16(bv[6], bv[7]) };
            *reinterpret_cast<uint4*>(&BY[p ^ 1][sts_off]) = qb;
        }
        __syncthreads();
    }

    uint32_t* obK = outK + (size_t)b * (ELEMS_PER_IMG / 2);
    uint32_t* obV = outV + (size_t)b * (ELEMS_PER_IMG / 2);
#pragma unroll
    for (int f = 0; f < 2; ++f) {
#pragma unroll
        for (int j = 0; j < 4; ++j) {
            const int row = m0 + wm + f * 16 + g;
            const int col = n0 + wn + j * 8 + 2 * t;
            const size_t i0 = ((size_t)row * HWSZ + col) >> 1;
            const size_t i1 = ((size_t)(row + 8) * HWSZ + col) >> 1;
            obK[i0] = pack_bf16(accK[f][j][0], accK[f][j][1]);
            obK[i1] = pack_bf16(accK[f][j][2], accK[f][j][3]);
            obV[i0] = pack_bf16(accV[f][j][0], accV[f][j][1]);
            obV[i1] = pack_bf16(accV[f][j][2], accV[f][j][3]);
        }
    }
}

// ============================================================================
// bf16 tensor-core attention per (b,c): S=Q@K -> softmax -> Z=M@V.
// 224 threads = 7 warps, warp w owns rows 16w..16w+15. m16n8k16: 7 k-steps.
// smem (bf16x2 words, pitch 56 = conflict-free): Ks/Vs [col j][kp] (transposed
// in staging via prmt), Ms [row][kp] holds Q then M. 75264 B -> 2 CTAs/SM.
// ============================================================================
#define PTW 56
#define TSZ (HH * PTW)                  // 6272 words
#define ATTN_SMEM (3 * TSZ * 4)         // 75264 B

__global__ void __launch_bounds__(224, 2)
attn_tc_kernel(const uint32_t* __restrict__ Qg, const uint32_t* __restrict__ Kg,
               const uint32_t* __restrict__ Vg, float* __restrict__ Z)
{
    extern __shared__ uint32_t smu[];
    uint32_t* Ks = smu;
    uint32_t* Vs = smu + TSZ;
    uint32_t* Ms = smu + 2 * TSZ;

    const size_t wbase = (size_t)blockIdx.x * (HWSZ / 2);   // word base
    const int tid  = threadIdx.x;
    const int wid  = tid >> 5;
    const int lane = tid & 31;
    const int g    = lane >> 2;
    const int t    = lane & 3;
    const int r0   = wid * 16;

    const uint32_t* Qb = Qg + wbase;
    const uint32_t* Kb = Kg + wbase;
    const uint32_t* Vb = Vg + wbase;

    // ---- stage Q: [row][jp] -> Ms[row][kslot(jp)] (cols are k) ----
    for (int i = tid; i < TSZ; i += 224) {
        const int row = i / PTW, jp = i % PTW;
        Ms[row * PTW + kslot(jp)] = Qb[i];
    }
    // ---- stage K,V transposed: [k][jp] -> [j][kslot(kp)] via prmt ----
    for (int i = tid; i < 56 * 56; i += 224) {
        const int kp = i / 56, jp = i % 56;
        const int s = kslot(kp);
        const int src0 = (2 * kp) * PTW + jp;
        const int src1 = (2 * kp + 1) * PTW + jp;
        uint32_t k0 = Kb[src0], k1 = Kb[src1];
        Ks[(2 * jp) * PTW + s]     = prmt(k0, k1, 0x5410);
        Ks[(2 * jp + 1) * PTW + s] = prmt(k0, k1, 0x7632);
        uint32_t v0 = Vb[src0], v1 = Vb[src1];
        Vs[(2 * jp) * PTW + s]     = prmt(v0, v1, 0x5410);
        Vs[(2 * jp + 1) * PTW + s] = prmt(v0, v1, 0x7632);
    }
    __syncthreads();

    float acc[14][4];
#pragma unroll
    for (int j = 0; j < 14; j++)
#pragma unroll
        for (int e = 0; e < 4; e++) acc[j][e] = 0.0f;

    // ---- S = Q @ K (7 k16 steps) ----
#pragma unroll
    for (int ks = 0; ks < 7; ++ks) {
        const int so = ks * 8 + 2 * t;
        uint2 lo = *reinterpret_cast<const uint2*>(&Ms[(r0 + g) * PTW + so]);
        uint2 hi = *reinterpret_cast<const uint2*>(&Ms[(r0 + g + 8) * PTW + so]);
        uint32_t a[4] = { lo.x, hi.x, lo.y, hi.y };
#pragma unroll
        for (int j = 0; j < 14; ++j) {
            uint2 bb = *reinterpret_cast<const uint2*>(&Ks[(j * 8 + g) * PTW + so]);
            uint32_t bfr[2] = { bb.x, bb.y };
            mma_bf16(acc[j], a, bfr);
        }
    }

    // ---- softmax (rows g -> c0,c1 ; rows g+8 -> c2,c3; quad reduce) ----
    {
        float mx0 = -1e30f, mx1 = -1e30f;
#pragma unroll
        for (int j = 0; j < 14; ++j) {
            mx0 = fmaxf(mx0, fmaxf(acc[j][0], acc[j][1]));
            mx1 = fmaxf(mx1, fmaxf(acc[j][2], acc[j][3]));
        }
        mx0 = fmaxf(mx0, __shfl_xor_sync(0xffffffffu, mx0, 1));
        mx0 = fmaxf(mx0, __shfl_xor_sync(0xffffffffu, mx0, 2));
        mx1 = fmaxf(mx1, __shfl_xor_sync(0xffffffffu, mx1, 1));
        mx1 = fmaxf(mx1, __shfl_xor_sync(0xffffffffu, mx1, 2));
        float s0 = 0.0f, s1 = 0.0f;
#pragma unroll
        for (int j = 0; j < 14; ++j) {
            acc[j][0] = __expf(acc[j][0] - mx0);
            acc[j][1] = __expf(acc[j][1] - mx0);
            acc[j][2] = __expf(acc[j][2] - mx1);
            acc[j][3] = __expf(acc[j][3] - mx1);
            s0 += acc[j][0] + acc[j][1];
            s1 += acc[j][2] + acc[j][3];
        }
        s0 += __shfl_xor_sync(0xffffffffu, s0, 1);
        s0 += __shfl_xor_sync(0xffffffffu, s0, 2);
        s1 += __shfl_xor_sync(0xffffffffu, s1, 1);
        s1 += __shfl_xor_sync(0xffffffffu, s1, 2);
        const float i0 = 1.0f / s0, i1 = 1.0f / s1;
#pragma unroll
        for (int j = 0; j < 14; ++j) {
            acc[j][0] *= i0; acc[j][1] *= i0;
            acc[j][2] *= i1; acc[j][3] *= i1;
        }
    }

    // ---- write M (bf16) into Ms (warp-private rows; Q fully consumed) ----
    __syncwarp();
#pragma unroll
    for (int j = 0; j < 14; ++j) {
        const int s = kslot(4 * j + t);          // cols (8j+2t, 8j+2t+1)
        Ms[(r0 + g) * PTW + s]     = pack_bf16(acc[j][0], acc[j][1]);
        Ms[(r0 + g + 8) * PTW + s] = pack_bf16(acc[j][2], acc[j][3]);
    }
    __syncwarp();

    // ---- Z = M @ V ----
#pragma unroll
    for (int j = 0; j < 14; j++)
#pragma unroll
        for (int e = 0; e < 4; e++) acc[j][e] = 0.0f;

#pragma unroll
    for (int ks = 0; ks < 7; ++ks) {
        const int so = ks * 8 + 2 * t;
        uint2 lo = *reinterpret_cast<const uint2*>(&Ms[(r0 + g) * PTW + so]);
        uint2 hi = *reinterpret_cast<const uint2*>(&Ms[(r0 + g + 8) * PTW + so]);
        uint32_t a[4] = { lo.x, hi.x, lo.y, hi.y };
#pragma unroll
        for (int j = 0; j < 14; ++j) {
            uint2 bb = *reinterpret_cast<const uint2*>(&Vs[(j * 8 + g) * PTW + so]);
            uint32_t bfr[2] = { bb.x, bb.y };
            mma_bf16(acc[j], a, bfr);
        }
    }

    // ---- store Z (float2, 8B-aligned) ----
    float* Zb = Z + (size_t)blockIdx.x * HWSZ;
#pragma unroll
    for (int j = 0; j < 14; ++j) {
        const int col = j * 8 + 2 * t;
        float2 v0 = { acc[j][0], acc[j][1] };
        float2 v1 = { acc[j][2], acc[j][3] };
        *reinterpret_cast<float2*>(&Zb[(r0 + g) * HH + col]) = v0;
        *reinterpret_cast<float2*>(&Zb[(r0 + g + 8) * HH + col]) = v1;
    }
}

extern "C" void kernel_launch(void* const* d_in, const int* in_sizes, int n_in,
                              void* d_out, int out_size)
{
    const float* x  = (const float*)d_in[0];
    const float* y  = (const float*)d_in[1];
    const float* WQ = (const float*)d_in[2];
    const float* WK = (const float*)d_in[3];
    const float* WV = (const float*)d_in[4];
    const float* WZ = (const float*)d_in[5];
    float* out = (float*)d_out;

    void *dQ, *dK, *dV, *dZ;
    cudaGetSymbolAddress(&dQ, g_Q);
    cudaGetSymbolAddress(&dK, g_K);
    cudaGetSymbolAddress(&dV, g_V);
    cudaGetSymbolAddress(&dZ, g_Zs);

    cudaFuncSetAttribute(attn_tc_kernel, cudaFuncAttributeMaxDynamicSharedMemorySize,
                         ATTN_SMEM);
    cudaFuncSetAttribute(gemm_tc_kernel, cudaFuncAttributeMaxDynamicSharedMemorySize,
                         GEMM_SMEM);
    cudaFuncSetAttribute(gemm_tc_kv_kernel, cudaFuncAttributeMaxDynamicSharedMemorySize,
                         KV_SMEM);

    dim3 gg(2, HWSZ / 128, BB);   // m-tile fastest -> B-tile L2 reuse

    gemm_tc_kernel<<<gg, 512, GEMM_SMEM>>>(WQ, x, nullptr, dQ, 1, 0);
    gemm_tc_kv_kernel<<<gg, 512, KV_SMEM>>>(WK, WV, y,
                                            (uint32_t*)dK, (uint32_t*)dV);
    attn_tc_kernel<<<BB * CC, 224, ATTN_SMEM>>>((const uint32_t*)dQ,
                                                (const uint32_t*)dK,
                                                (const uint32_t*)dV,
                                                (float*)dZ);
    gemm_tc_kernel<<<gg, 512, GEMM_SMEM>>>(WZ, (const float*)dZ, x, out, 0, 1);
}

// round 11
// speedup vs baseline: 2.4815x; 1.1070x over previous
#include <cuda_runtime.h>
#include <cuda_bf16.h>
#include <cstdint>

// Problem constants
#define BB 8
#define CC 256
#define HH 112
#define HWSZ 12544              // 112*112
#define ELEMS_PER_IMG (CC * HWSZ)
#define TOTAL_ELEMS (BB * ELEMS_PER_IMG)

// Scratch (device globals; no allocations allowed)
__device__ __nv_bfloat16 g_Q[TOTAL_ELEMS];
__device__ __nv_bfloat16 g_K[TOTAL_ELEMS];
__device__ __nv_bfloat16 g_V[TOTAL_ELEMS];
__device__ float         g_Zs[TOTAL_ELEMS];

// pack two floats into bf16x2: lo -> low half, hi -> high half
__device__ __forceinline__ uint32_t pack_bf16(float lo, float hi) {
    uint32_t r;
    asm("cvt.rn.bf16x2.f32 %0, %1, %2;" : "=r"(r) : "f"(hi), "f"(lo));
    return r;
}
__device__ __forceinline__ uint32_t prmt(uint32_t a, uint32_t b, uint32_t sel) {
    uint32_t r;
    asm("prmt.b32 %0, %1, %2, %3;" : "=r"(r) : "r"(a), "r"(b), "r"(sel));
    return r;
}

// mma.sync m16n8k16 bf16 (baseline PTX; fragment layout validated R9/R10)
__device__ __forceinline__ void mma_bf16(float* c, const uint32_t* a, const uint32_t* b) {
    asm volatile(
        "mma.sync.aligned.m16n8k16.row.col.f32.bf16.bf16.f32 "
        "{%0,%1,%2,%3}, {%4,%5,%6,%7}, {%8,%9}, {%0,%1,%2,%3};"
        : "+f"(c[0]), "+f"(c[1]), "+f"(c[2]), "+f"(c[3])
        : "r"(a[0]), "r"(a[1]), "r"(a[2]), "r"(a[3]), "r"(b[0]), "r"(b[1]));
}

// k-pair interleave slot within 8-word k16 group (validated R9):
// kp = 8*ks + u ; slot = 8*ks + (u<4 ? 2u : 2u-7)
__device__ __forceinline__ int kslot(int kp) {
    const int u = kp & 7;
    return (kp & ~7) + ((u < 4) ? (2 * u) : (2 * u - 7));
}

// ============================================================================
// bf16 tensor-core GEMM: out = W @ in (+res+relu if float out)
// CTA 128x128, 256 threads (8 warps 2x4), warp tile 64x32 (4 m-frags x 4 n).
// K=256 in 8 chunks of 32, double-buffered, register-prefetched.
// Pitch 40 words: fragment LDS.64 fully bank-conflict-free per half-warp.
// ============================================================================
#define PAB 40
#define TILE_W (128 * PAB)                   // 5120 words
#define GEMM_SMEM (4 * TILE_W * 4)           // 81920 B

__global__ void __launch_bounds__(256, 2)
gemm_tc_kernel(const float* __restrict__ Wmat,
               const float* __restrict__ in,
               const float* __restrict__ res,
               void* __restrict__ outp,
               int out_bf16, int do_relu)
{
    extern __shared__ uint32_t smu[];
    uint32_t* Abuf[2] = { smu,              smu + 2 * TILE_W };
    uint32_t* Bbuf[2] = { smu + TILE_W,     smu + 3 * TILE_W };

    const int tid  = threadIdx.x;
    const int wid  = tid >> 5;
    const int lane = tid & 31;
    const int g    = lane >> 2;
    const int t    = lane & 3;
    const int wm   = (wid >> 2) * 64;        // 0 or 64
    const int wn   = (wid & 3) * 32;

    const int m0 = blockIdx.x * 128;
    const int n0 = blockIdx.y * 128;
    const int b  = blockIdx.z;
    const float* inb = in + (size_t)b * ELEMS_PER_IMG;

    // staging: 512 uint4 slots per operand; thread owns slots tid, tid+256
    // slot s: rr = s & 127 (row for A / col for B), q = s >> 7 (quad 0..3)
    const int rr = tid & 127;
    const int q0 = tid >> 7;                 // 0..1
    const int q1 = q0 + 2;                   // 2..3

    float acc[4][4][4];
#pragma unroll
    for (int f = 0; f < 4; f++)
#pragma unroll
        for (int j = 0; j < 4; j++)
#pragma unroll
            for (int e = 0; e < 4; e++) acc[f][j][e] = 0.0f;

    uint32_t pa[2][4], pb[2][4];

    // ---- chunk loader: global -> packed bf16x2 regs ----
    auto load_chunk = [&](int kk) {
#pragma unroll
        for (int it = 0; it < 2; ++it) {
            const int q  = it ? q1 : q0;
            const int kb = kk + (q >> 1) * 16 + (q & 1) * 4;
            const float* arow = &Wmat[(m0 + rr) * CC + kb];
            float4 a0 = *reinterpret_cast<const float4*>(arow);
            float4 a1 = *reinterpret_cast<const float4*>(arow + 8);
            pa[it][0] = pack_bf16(a0.x, a0.y);
            pa[it][1] = pack_bf16(a1.x, a1.y);
            pa[it][2] = pack_bf16(a0.z, a0.w);
            pa[it][3] = pack_bf16(a1.z, a1.w);
            const float* bc = &inb[(size_t)kb * HWSZ + n0 + rr];
            float b0 = bc[0];
            float b1 = bc[HWSZ];
            float b2 = bc[2 * (size_t)HWSZ];
            float b3 = bc[3 * (size_t)HWSZ];
            float b4 = bc[8 * (size_t)HWSZ];
            float b5 = bc[9 * (size_t)HWSZ];
            float b6 = bc[10 * (size_t)HWSZ];
            float b7 = bc[11 * (size_t)HWSZ];
            pb[it][0] = pack_bf16(b0, b1);
            pb[it][1] = pack_bf16(b4, b5);
            pb[it][2] = pack_bf16(b2, b3);
            pb[it][3] = pack_bf16(b6, b7);
        }
    };
    auto store_chunk = [&](int p) {
#pragma unroll
        for (int it = 0; it < 2; ++it) {
            const int q = it ? q1 : q0;
            *reinterpret_cast<uint4*>(&Abuf[p][rr * PAB + q * 4]) =
                *reinterpret_cast<uint4*>(pa[it]);
            *reinterpret_cast<uint4*>(&Bbuf[p][rr * PAB + q * 4]) =
                *reinterpret_cast<uint4*>(pb[it]);
        }
    };

    load_chunk(0);
    store_chunk(0);
    __syncthreads();

    for (int i = 0; i < 8; ++i) {
        const int p = i & 1;

        if (i < 7) load_chunk((i + 1) * 32);   // prefetch into regs

        const uint32_t* As = Abuf[p];
        const uint32_t* Bs = Bbuf[p];
#pragma unroll
        for (int ks = 0; ks < 2; ++ks) {
            const int so = ks * 8 + 2 * t;
            uint32_t afr[4][4];
#pragma unroll
            for (int f = 0; f < 4; ++f) {
                const int row = wm + f * 16 + g;
                uint2 lo = *reinterpret_cast<const uint2*>(&As[row * PAB + so]);
                uint2 hi = *reinterpret_cast<const uint2*>(&As[(row + 8) * PAB + so]);
                afr[f][0] = lo.x; afr[f][1] = hi.x;
                afr[f][2] = lo.y; afr[f][3] = hi.y;
            }
#pragma unroll
            for (int j = 0; j < 4; ++j) {
                const int col = wn + j * 8 + g;
                uint2 bb = *reinterpret_cast<const uint2*>(&Bs[col * PAB + so]);
                uint32_t bfr[2] = { bb.x, bb.y };
#pragma unroll
                for (int f = 0; f < 4; ++f)
                    mma_bf16(acc[f][j], afr[f], bfr);
            }
        }

        if (i < 7) store_chunk(p ^ 1);
        __syncthreads();
    }

    // ---- epilogue ----
    if (out_bf16) {
        uint32_t* ob = reinterpret_cast<uint32_t*>(outp) + (size_t)b * (ELEMS_PER_IMG / 2);
#pragma unroll
        for (int f = 0; f < 4; ++f) {
#pragma unroll
            for (int j = 0; j < 4; ++j) {
                const int row = m0 + wm + f * 16 + g;
                const int col = n0 + wn + j * 8 + 2 * t;   // even
                ob[((size_t)row * HWSZ + col) >> 1]       = pack_bf16(acc[f][j][0], acc[f][j][1]);
                ob[((size_t)(row + 8) * HWSZ + col) >> 1] = pack_bf16(acc[f][j][2], acc[f][j][3]);
            }
        }
    } else {
        float* outb = reinterpret_cast<float*>(outp) + (size_t)b * ELEMS_PER_IMG;
        const float* resb = res ? res + (size_t)b * ELEMS_PER_IMG : nullptr;
#pragma unroll
        for (int f = 0; f < 4; ++f) {
#pragma unroll
            for (int j = 0; j < 4; ++j) {
                const int row = m0 + wm + f * 16 + g;
                const int col = n0 + wn + j * 8 + 2 * t;
                float2 v0 = { acc[f][j][0], acc[f][j][1] };
                float2 v1 = { acc[f][j][2], acc[f][j][3] };
                if (do_relu) {
                    float2 r0 = *reinterpret_cast<const float2*>(&resb[(size_t)row * HWSZ + col]);
                    float2 r1 = *reinterpret_cast<const float2*>(&resb[(size_t)(row + 8) * HWSZ + col]);
                    v0.x = fmaxf(v0.x + r0.x, 0.0f);
                    v0.y = fmaxf(v0.y + r0.y, 0.0f);
                    v1.x = fmaxf(v1.x + r1.x, 0.0f);
                    v1.y = fmaxf(v1.y + r1.y, 0.0f);
                }
                *reinterpret_cast<float2*>(&outb[(size_t)row * HWSZ + col]) = v0;
                *reinterpret_cast<float2*>(&outb[(size_t)(row + 8) * HWSZ + col]) = v1;
            }
        }
    }
}

// ============================================================================
// bf16 tensor-core attention per (b,c) — unchanged from R10 passing version.
// ============================================================================
#define PTW 56
#define TSZ (HH * PTW)                  // 6272 words
#define ATTN_SMEM (3 * TSZ * 4)         // 75264 B

__global__ void __launch_bounds__(224, 2)
attn_tc_kernel(const uint32_t* __restrict__ Qg, const uint32_t* __restrict__ Kg,
               const uint32_t* __restrict__ Vg, float* __restrict__ Z)
{
    extern __shared__ uint32_t smu[];
    uint32_t* Ks = smu;
    uint32_t* Vs = smu + TSZ;
    uint32_t* Ms = smu + 2 * TSZ;

    const size_t wbase = (size_t)blockIdx.x * (HWSZ / 2);
    const int tid  = threadIdx.x;
    const int wid  = tid >> 5;
    const int lane = tid & 31;
    const int g    = lane >> 2;
    const int t    = lane & 3;
    const int r0   = wid * 16;

    const uint32_t* Qb = Qg + wbase;
    const uint32_t* Kb = Kg + wbase;
    const uint32_t* Vb = Vg + wbase;

    for (int i = tid; i < TSZ; i += 224) {
        const int row = i / PTW, jp = i % PTW;
        Ms[row * PTW + kslot(jp)] = Qb[i];
    }
    for (int i = tid; i < 56 * 56; i += 224) {
        const int kp = i / 56, jp = i % 56;
        const int s = kslot(kp);
        const int src0 = (2 * kp) * PTW + jp;
        const int src1 = (2 * kp + 1) * PTW + jp;
        uint32_t k0 = Kb[src0], k1 = Kb[src1];
        Ks[(2 * jp) * PTW + s]     = prmt(k0, k1, 0x5410);
        Ks[(2 * jp + 1) * PTW + s] = prmt(k0, k1, 0x7632);
        uint32_t v0 = Vb[src0], v1 = Vb[src1];
        Vs[(2 * jp) * PTW + s]     = prmt(v0, v1, 0x5410);
        Vs[(2 * jp + 1) * PTW + s] = prmt(v0, v1, 0x7632);
    }
    __syncthreads();

    float acc[14][4];
#pragma unroll
    for (int j = 0; j < 14; j++)
#pragma unroll
        for (int e = 0; e < 4; e++) acc[j][e] = 0.0f;

#pragma unroll
    for (int ks = 0; ks < 7; ++ks) {
        const int so = ks * 8 + 2 * t;
        uint2 lo = *reinterpret_cast<const uint2*>(&Ms[(r0 + g) * PTW + so]);
        uint2 hi = *reinterpret_cast<const uint2*>(&Ms[(r0 + g + 8) * PTW + so]);
        uint32_t a[4] = { lo.x, hi.x, lo.y, hi.y };
#pragma unroll
        for (int j = 0; j < 14; ++j) {
            uint2 bb = *reinterpret_cast<const uint2*>(&Ks[(j * 8 + g) * PTW + so]);
            uint32_t bfr[2] = { bb.x, bb.y };
            mma_bf16(acc[j], a, bfr);
        }
    }

    {
        float mx0 = -1e30f, mx1 = -1e30f;
#pragma unroll
        for (int j = 0; j < 14; ++j) {
            mx0 = fmaxf(mx0, fmaxf(acc[j][0], acc[j][1]));
            mx1 = fmaxf(mx1, fmaxf(acc[j][2], acc[j][3]));
        }
        mx0 = fmaxf(mx0, __shfl_xor_sync(0xffffffffu, mx0, 1));
        mx0 = fmaxf(mx0, __shfl_xor_sync(0xffffffffu, mx0, 2));
        mx1 = fmaxf(mx1, __shfl_xor_sync(0xffffffffu, mx1, 1));
        mx1 = fmaxf(mx1, __shfl_xor_sync(0xffffffffu, mx1, 2));
        float s0 = 0.0f, s1 = 0.0f;
#pragma unroll
        for (int j = 0; j < 14; ++j) {
            acc[j][0] = __expf(acc[j][0] - mx0);
            acc[j][1] = __expf(acc[j][1] - mx0);
            acc[j][2] = __expf(acc[j][2] - mx1);
            acc[j][3] = __expf(acc[j][3] - mx1);
            s0 += acc[j][0] + acc[j][1];
            s1 += acc[j][2] + acc[j][3];
        }
        s0 += __shfl_xor_sync(0xffffffffu, s0, 1);
        s0 += __shfl_xor_sync(0xffffffffu, s0, 2);
        s1 += __shfl_xor_sync(0xffffffffu, s1, 1);
        s1 += __shfl_xor_sync(0xffffffffu, s1, 2);
        const float i0 = 1.0f / s0, i1 = 1.0f / s1;
#pragma unroll
        for (int j = 0; j < 14; ++j) {
            acc[j][0] *= i0; acc[j][1] *= i0;
            acc[j][2] *= i1; acc[j][3] *= i1;
        }
    }

    __syncwarp();
#pragma unroll
    for (int j = 0; j < 14; ++j) {
        const int s = kslot(4 * j + t);
        Ms[(r0 + g) * PTW + s]     = pack_bf16(acc[j][0], acc[j][1]);
        Ms[(r0 + g + 8) * PTW + s] = pack_bf16(acc[j][2], acc[j][3]);
    }
    __syncwarp();

#pragma unroll
    for (int j = 0; j < 14; j++)
#pragma unroll
        for (int e = 0; e < 4; e++) acc[j][e] = 0.0f;

#pragma unroll
    for (int ks = 0; ks < 7; ++ks) {
        const int so = ks * 8 + 2 * t;
        uint2 lo = *reinterpret_cast<const uint2*>(&Ms[(r0 + g) * PTW + so]);
        uint2 hi = *reinterpret_cast<const uint2*>(&Ms[(r0 + g + 8) * PTW + so]);
        uint32_t a[4] = { lo.x, hi.x, lo.y, hi.y };
#pragma unroll
        for (int j = 0; j < 14; ++j) {
            uint2 bb = *reinterpret_cast<const uint2*>(&Vs[(j * 8 + g) * PTW + so]);
            uint32_t bfr[2] = { bb.x, bb.y };
            mma_bf16(acc[j], a, bfr);
        }
    }

    float* Zb = Z + (size_t)blockIdx.x * HWSZ;
#pragma unroll
    for (int j = 0; j < 14; ++j) {
        const int col = j * 8 + 2 * t;
        float2 v0 = { acc[j][0], acc[j][1] };
        float2 v1 = { acc[j][2], acc[j][3] };
        *reinterpret_cast<float2*>(&Zb[(r0 + g) * HH + col]) = v0;
        *reinterpret_cast<float2*>(&Zb[(r0 + g + 8) * HH + col]) = v1;
    }
}

extern "C" void kernel_launch(void* const* d_in, const int* in_sizes, int n_in,
                              void* d_out, int out_size)
{
    const float* x  = (const float*)d_in[0];
    const float* y  = (const float*)d_in[1];
    const float* WQ = (const float*)d_in[2];
    const float* WK = (const float*)d_in[3];
    const float* WV = (const float*)d_in[4];
    const float* WZ = (const float*)d_in[5];
    float* out = (float*)d_out;

    void *dQ, *dK, *dV, *dZ;
    cudaGetSymbolAddress(&dQ, g_Q);
    cudaGetSymbolAddress(&dK, g_K);
    cudaGetSymbolAddress(&dV, g_V);
    cudaGetSymbolAddress(&dZ, g_Zs);

    cudaFuncSetAttribute(attn_tc_kernel, cudaFuncAttributeMaxDynamicSharedMemorySize,
                         ATTN_SMEM);
    cudaFuncSetAttribute(gemm_tc_kernel, cudaFuncAttributeMaxDynamicSharedMemorySize,
                         GEMM_SMEM);

    dim3 gg(2, HWSZ / 128, BB);   // m-tile fastest -> B-tile L2 reuse

    gemm_tc_kernel<<<gg, 256, GEMM_SMEM>>>(WQ, x, nullptr, dQ, 1, 0);
    gemm_tc_kernel<<<gg, 256, GEMM_SMEM>>>(WK, y, nullptr, dK, 1, 0);
    gemm_tc_kernel<<<gg, 256, GEMM_SMEM>>>(WV, y, nullptr, dV, 1, 0);
    attn_tc_kernel<<<BB * CC, 224, ATTN_SMEM>>>((const uint32_t*)dQ,
                                                (const uint32_t*)dK,
                                                (const uint32_t*)dV,
                                                (float*)dZ);
    gemm_tc_kernel<<<gg, 256, GEMM_SMEM>>>(WZ, (const float*)dZ, x, out, 0, 1);
}

// round 12
// speedup vs baseline: 3.0113x; 1.2135x over previous
#include <cuda_runtime.h>
#include <cuda_bf16.h>
#include <cstdint>

// Problem constants
#define BB 8
#define CC 256
#define HH 112
#define HWSZ 12544              // 112*112
#define ELEMS_PER_IMG (CC * HWSZ)
#define TOTAL_ELEMS (BB * ELEMS_PER_IMG)

// Scratch (device globals; no allocations allowed)
__device__ __nv_bfloat16 g_Q[TOTAL_ELEMS];
__device__ __nv_bfloat16 g_K[TOTAL_ELEMS];
__device__ __nv_bfloat16 g_V[TOTAL_ELEMS];
__device__ float         g_Zs[TOTAL_ELEMS];

__device__ __forceinline__ uint32_t smem_u32(const void* p) {
    uint32_t a;
    asm("{ .reg .u64 t; cvta.to.shared.u64 t, %1; cvt.u32.u64 %0, t; }"
        : "=r"(a) : "l"(p));
    return a;
}
// pack two floats into bf16x2: lo -> low half, hi -> high half
__device__ __forceinline__ uint32_t pack_bf16(float lo, float hi) {
    uint32_t r;
    asm("cvt.rn.bf16x2.f32 %0, %1, %2;" : "=r"(r) : "f"(hi), "f"(lo));
    return r;
}
__device__ __forceinline__ uint32_t prmt(uint32_t a, uint32_t b, uint32_t sel) {
    uint32_t r;
    asm("prmt.b32 %0, %1, %2, %3;" : "=r"(r) : "r"(a), "r"(b), "r"(sel));
    return r;
}
// ldmatrix x4: 4 8x8 b16 matrices; lane groups 0-7/8-15/16-23/24-31 give the
// row addresses of matrices 0..3; reg i = matrix i.
__device__ __forceinline__ void ldsm_x4(uint32_t* r, uint32_t addr) {
    asm volatile("ldmatrix.sync.aligned.m8n8.x4.shared.b16 {%0,%1,%2,%3}, [%4];"
        : "=r"(r[0]), "=r"(r[1]), "=r"(r[2]), "=r"(r[3]) : "r"(addr));
}
// mma.sync m16n8k16 bf16 (baseline PTX; fragment layout validated R9-R11)
__device__ __forceinline__ void mma_bf16(float* c, const uint32_t* a, const uint32_t* b) {
    asm volatile(
        "mma.sync.aligned.m16n8k16.row.col.f32.bf16.bf16.f32 "
        "{%0,%1,%2,%3}, {%4,%5,%6,%7}, {%8,%9}, {%0,%1,%2,%3};"
        : "+f"(c[0]), "+f"(c[1]), "+f"(c[2]), "+f"(c[3])
        : "r"(a[0]), "r"(a[1]), "r"(a[2]), "r"(a[3]), "r"(b[0]), "r"(b[1]));
}

// ============================================================================
// bf16 tensor-core GEMM: out = W @ in (+res+relu if float out)
// CTA 128x128, 256 threads (8 warps 2x4), warp tile 64x32.
// smem: natural [row][k] bf16, pitch 36 words (144B) -> LDSM/STS conflict-free.
// Fragments via ldmatrix.x4: per k16-step 4 A-LDSM + 2 B-LDSM feed 16 MMAs.
// ============================================================================
#define PAB 36
#define TILE_W (128 * PAB)                   // 4608 words
#define GEMM_SMEM (4 * TILE_W * 4)           // 73728 B

__global__ void __launch_bounds__(256, 2)
gemm_tc_kernel(const float* __restrict__ Wmat,
               const float* __restrict__ in,
               const float* __restrict__ res,
               void* __restrict__ outp,
               int out_bf16, int do_relu)
{
    extern __shared__ uint32_t smu[];
    const uint32_t smb = smem_u32(smu);
    uint32_t* Abuf[2] = { smu,              smu + 2 * TILE_W };
    uint32_t* Bbuf[2] = { smu + TILE_W,     smu + 3 * TILE_W };
    const uint32_t abase[2] = { smb,                    smb + 2 * TILE_W * 4 };
    const uint32_t bbase[2] = { smb + TILE_W * 4,       smb + 3 * TILE_W * 4 };

    const int tid  = threadIdx.x;
    const int wid  = tid >> 5;
    const int lane = tid & 31;
    const int g    = lane >> 2;
    const int t    = lane & 3;
    const int wm   = (wid >> 2) * 64;        // 0 or 64
    const int wn   = (wid & 3) * 32;

    const int m0 = blockIdx.x * 128;
    const int n0 = blockIdx.y * 128;
    const int b  = blockIdx.z;
    const float* inb = in + (size_t)b * ELEMS_PER_IMG;

    // ldmatrix per-lane byte offsets (within a tile)
    const uint32_t aoff = ((wm + (lane & 15)) * PAB + ((lane >> 4) << 2)) * 4;
    const uint32_t boff = (((lane & 7) + ((lane >> 4) << 3)) * PAB
                           + (((lane >> 3) & 1) << 2)) * 4;

    // staging: thread owns (rr, q0) and (rr, q1); quad q covers k = q*8..q*8+7
    const int rr = tid & 127;
    const int q0 = tid >> 7;                 // 0..1
    const int q1 = q0 + 2;                   // 2..3

    float acc[4][4][4];
#pragma unroll
    for (int f = 0; f < 4; f++)
#pragma unroll
        for (int j = 0; j < 4; j++)
#pragma unroll
            for (int e = 0; e < 4; e++) acc[f][j][e] = 0.0f;

    uint32_t pa[2][4], pb[2][4];

    auto load_chunk = [&](int kk) {
#pragma unroll
        for (int it = 0; it < 2; ++it) {
            const int q  = it ? q1 : q0;
            const int kb = kk + q * 8;
            const float* arow = &Wmat[(m0 + rr) * CC + kb];
            float4 a0 = *reinterpret_cast<const float4*>(arow);
            float4 a1 = *reinterpret_cast<const float4*>(arow + 4);
            pa[it][0] = pack_bf16(a0.x, a0.y);
            pa[it][1] = pack_bf16(a0.z, a0.w);
            pa[it][2] = pack_bf16(a1.x, a1.y);
            pa[it][3] = pack_bf16(a1.z, a1.w);
            const float* bc = &inb[(size_t)kb * HWSZ + n0 + rr];
            float b0 = bc[0];
            float b1 = bc[HWSZ];
            float b2 = bc[2 * (size_t)HWSZ];
            float b3 = bc[3 * (size_t)HWSZ];
            float b4 = bc[4 * (size_t)HWSZ];
            float b5 = bc[5 * (size_t)HWSZ];
            float b6 = bc[6 * (size_t)HWSZ];
            float b7 = bc[7 * (size_t)HWSZ];
            pb[it][0] = pack_bf16(b0, b1);
            pb[it][1] = pack_bf16(b2, b3);
            pb[it][2] = pack_bf16(b4, b5);
            pb[it][3] = pack_bf16(b6, b7);
        }
    };
    auto store_chunk = [&](int p) {
#pragma unroll
        for (int it = 0; it < 2; ++it) {
            const int q = it ? q1 : q0;
            *reinterpret_cast<uint4*>(&Abuf[p][rr * PAB + q * 4]) =
                *reinterpret_cast<uint4*>(pa[it]);
            *reinterpret_cast<uint4*>(&Bbuf[p][rr * PAB + q * 4]) =
                *reinterpret_cast<uint4*>(pb[it]);
        }
    };

    load_chunk(0);
    store_chunk(0);
    __syncthreads();

    for (int i = 0; i < 8; ++i) {
        const int p = i & 1;

        if (i < 7) load_chunk((i + 1) * 32);   // prefetch into regs

        const uint32_t aA = abase[p] + aoff;
        const uint32_t aB = bbase[p] + boff;
#pragma unroll
        for (int ks = 0; ks < 2; ++ks) {
            uint32_t afr[4][4];
#pragma unroll
            for (int f = 0; f < 4; ++f)
                ldsm_x4(afr[f], aA + f * (16 * PAB * 4) + ks * 32);
#pragma unroll
            for (int j2 = 0; j2 < 2; ++j2) {
                uint32_t bfr[4];
                ldsm_x4(bfr, aB + (wn + j2 * 16) * (PAB * 4) + ks * 32);
#pragma unroll
                for (int f = 0; f < 4; ++f) {
                    mma_bf16(acc[f][2 * j2],     afr[f], bfr);
                    mma_bf16(acc[f][2 * j2 + 1], afr[f], bfr + 2);
                }
            }
        }

        if (i < 7) store_chunk(p ^ 1);
        __syncthreads();
    }

    // ---- epilogue ----
    if (out_bf16) {
        uint32_t* ob = reinterpret_cast<uint32_t*>(outp) + (size_t)b * (ELEMS_PER_IMG / 2);
#pragma unroll
        for (int f = 0; f < 4; ++f) {
#pragma unroll
            for (int j = 0; j < 4; ++j) {
                const int row = m0 + wm + f * 16 + g;
                const int col = n0 + wn + j * 8 + 2 * t;   // even
                ob[((size_t)row * HWSZ + col) >> 1]       = pack_bf16(acc[f][j][0], acc[f][j][1]);
                ob[((size_t)(row + 8) * HWSZ + col) >> 1] = pack_bf16(acc[f][j][2], acc[f][j][3]);
            }
        }
    } else {
        float* outb = reinterpret_cast<float*>(outp) + (size_t)b * ELEMS_PER_IMG;
        const float* resb = res ? res + (size_t)b * ELEMS_PER_IMG : nullptr;
#pragma unroll
        for (int f = 0; f < 4; ++f) {
#pragma unroll
            for (int j = 0; j < 4; ++j) {
                const int row = m0 + wm + f * 16 + g;
                const int col = n0 + wn + j * 8 + 2 * t;
                float2 v0 = { acc[f][j][0], acc[f][j][1] };
                float2 v1 = { acc[f][j][2], acc[f][j][3] };
                if (do_relu) {
                    float2 r0 = *reinterpret_cast<const float2*>(&resb[(size_t)row * HWSZ + col]);
                    float2 r1 = *reinterpret_cast<const float2*>(&resb[(size_t)(row + 8) * HWSZ + col]);
                    v0.x = fmaxf(v0.x + r0.x, 0.0f);
                    v0.y = fmaxf(v0.y + r0.y, 0.0f);
                    v1.x = fmaxf(v1.x + r1.x, 0.0f);
                    v1.y = fmaxf(v1.y + r1.y, 0.0f);
                }
                *reinterpret_cast<float2*>(&outb[(size_t)row * HWSZ + col]) = v0;
                *reinterpret_cast<float2*>(&outb[(size_t)(row + 8) * HWSZ + col]) = v1;
            }
        }
    }
}

// ============================================================================
// bf16 tensor-core attention per (b,c), ldmatrix fragments.
// 224 threads = 7 warps, warp w owns rows 16w..16w+15.
// smem natural [row][k] bf16, pitch 60 words (240B) -> conflict-free LDSM.
// ============================================================================
#define PTQ 60
#define ATSZ (HH * PTQ)                 // 6720 words
#define ATTN_SMEM (3 * ATSZ * 4)        // 80640 B

__global__ void __launch_bounds__(224, 2)
attn_tc_kernel(const uint32_t* __restrict__ Qg, const uint32_t* __restrict__ Kg,
               const uint32_t* __restrict__ Vg, float* __restrict__ Z)
{
    extern __shared__ uint32_t smu[];
    const uint32_t smb = smem_u32(smu);
    uint32_t* Ks = smu;
    uint32_t* Vs = smu + ATSZ;
    uint32_t* Ms = smu + 2 * ATSZ;
    const uint32_t kbase = smb;
    const uint32_t vbase = smb + ATSZ * 4;
    const uint32_t mbase = smb + 2 * ATSZ * 4;

    const size_t wbase = (size_t)blockIdx.x * (HWSZ / 2);
    const int tid  = threadIdx.x;
    const int wid  = tid >> 5;
    const int lane = tid & 31;
    const int g    = lane >> 2;
    const int t    = lane & 3;
    const int r0   = wid * 16;

    const uint32_t* Qb = Qg + wbase;
    const uint32_t* Kb = Kg + wbase;
    const uint32_t* Vb = Vg + wbase;

    // stage Q: [row][k-pair] direct copy into pitch-60 layout
    for (int i = tid; i < HWSZ / 2; i += 224) {
        const int row = i / 56, jp = i % 56;
        Ms[row * PTQ + jp] = Qb[i];
    }
    // stage K,V transposed: global [k][n] -> smem [n][k-pair] via prmt
    for (int i = tid; i < 56 * 56; i += 224) {
        const int kp = i / 56, jp = i % 56;
        const int src0 = (2 * kp) * 56 + jp;
        const int src1 = (2 * kp + 1) * 56 + jp;
        uint32_t k0 = Kb[src0], k1 = Kb[src1];
        Ks[(2 * jp) * PTQ + kp]     = prmt(k0, k1, 0x5410);
        Ks[(2 * jp + 1) * PTQ + kp] = prmt(k0, k1, 0x7632);
        uint32_t v0 = Vb[src0], v1 = Vb[src1];
        Vs[(2 * jp) * PTQ + kp]     = prmt(v0, v1, 0x5410);
        Vs[(2 * jp + 1) * PTQ + kp] = prmt(v0, v1, 0x7632);
    }
    __syncthreads();

    // ldmatrix per-lane byte offsets
    const uint32_t aoff = ((r0 + (lane & 15)) * PTQ + ((lane >> 4) << 2)) * 4;
    const uint32_t boff = (((lane & 7) + ((lane >> 4) << 3)) * PTQ
                           + (((lane >> 3) & 1) << 2)) * 4;

    float acc[14][4];
#pragma unroll
    for (int j = 0; j < 14; j++)
#pragma unroll
        for (int e = 0; e < 4; e++) acc[j][e] = 0.0f;

    // ---- S = Q @ K (7 k16 steps) ----
#pragma unroll
    for (int ks = 0; ks < 7; ++ks) {
        uint32_t a[4];
        ldsm_x4(a, mbase + aoff + ks * 32);
#pragma unroll
        for (int j2 = 0; j2 < 7; ++j2) {
            uint32_t bfr[4];
            ldsm_x4(bfr, kbase + boff + j2 * (16 * PTQ * 4) + ks * 32);
            mma_bf16(acc[2 * j2],     a, bfr);
            mma_bf16(acc[2 * j2 + 1], a, bfr + 2);
        }
    }

    // ---- softmax ----
    {
        float mx0 = -1e30f, mx1 = -1e30f;
#pragma unroll
        for (int j = 0; j < 14; ++j) {
            mx0 = fmaxf(mx0, fmaxf(acc[j][0], acc[j][1]));
            mx1 = fmaxf(mx1, fmaxf(acc[j][2], acc[j][3]));
        }
        mx0 = fmaxf(mx0, __shfl_xor_sync(0xffffffffu, mx0, 1));
        mx0 = fmaxf(mx0, __shfl_xor_sync(0xffffffffu, mx0, 2));
        mx1 = fmaxf(mx1, __shfl_xor_sync(0xffffffffu, mx1, 1));
        mx1 = fmaxf(mx1, __shfl_xor_sync(0xffffffffu, mx1, 2));
        float s0 = 0.0f, s1 = 0.0f;
#pragma unroll
        for (int j = 0; j < 14; ++j) {
            acc[j][0] = __expf(acc[j][0] - mx0);
            acc[j][1] = __expf(acc[j][1] - mx0);
            acc[j][2] = __expf(acc[j][2] - mx1);
            acc[j][3] = __expf(acc[j][3] - mx1);
            s0 += acc[j][0] + acc[j][1];
            s1 += acc[j][2] + acc[j][3];
        }
        s0 += __shfl_xor_sync(0xffffffffu, s0, 1);
        s0 += __shfl_xor_sync(0xffffffffu, s0, 2);
        s1 += __shfl_xor_sync(0xffffffffu, s1, 1);
        s1 += __shfl_xor_sync(0xffffffffu, s1, 2);
        const float i0 = 1.0f / s0, i1 = 1.0f / s1;
#pragma unroll
        for (int j = 0; j < 14; ++j) {
            acc[j][0] *= i0; acc[j][1] *= i0;
            acc[j][2] *= i1; acc[j][3] *= i1;
        }
    }

    // ---- write M (bf16, contiguous words) into Ms; rows are warp-private ----
    __syncwarp();
#pragma unroll
    for (int j = 0; j < 14; ++j) {
        Ms[(r0 + g) * PTQ + j * 4 + t]     = pack_bf16(acc[j][0], acc[j][1]);
        Ms[(r0 + g + 8) * PTQ + j * 4 + t] = pack_bf16(acc[j][2], acc[j][3]);
    }
    __syncwarp();

    // ---- Z = M @ V ----
#pragma unroll
    for (int j = 0; j < 14; j++)
#pragma unroll
        for (int e = 0; e < 4; e++) acc[j][e] = 0.0f;

#pragma unroll
    for (int ks = 0; ks < 7; ++ks) {
        uint32_t a[4];
        ldsm_x4(a, mbase + aoff + ks * 32);
#pragma unroll
        for (int j2 = 0; j2 < 7; ++j2) {
            uint32_t bfr[4];
            ldsm_x4(bfr, vbase + boff + j2 * (16 * PTQ * 4) + ks * 32);
            mma_bf16(acc[2 * j2],     a, bfr);
            mma_bf16(acc[2 * j2 + 1], a, bfr + 2);
        }
    }

    // ---- store Z (float2, 8B-aligned) ----
    float* Zb = Z + (size_t)blockIdx.x * HWSZ;
#pragma unroll
    for (int j = 0; j < 14; ++j) {
        const int col = j * 8 + 2 * t;
        float2 v0 = { acc[j][0], acc[j][1] };
        float2 v1 = { acc[j][2], acc[j][3] };
        *reinterpret_cast<float2*>(&Zb[(r0 + g) * HH + col]) = v0;
        *reinterpret_cast<float2*>(&Zb[(r0 + g + 8) * HH + col]) = v1;
    }
}

extern "C" void kernel_launch(void* const* d_in, const int* in_sizes, int n_in,
                              void* d_out, int out_size)
{
    const float* x  = (const float*)d_in[0];
    const float* y  = (const float*)d_in[1];
    const float* WQ = (const float*)d_in[2];
    const float* WK = (const float*)d_in[3];
    const float* WV = (const float*)d_in[4];
    const float* WZ = (const float*)d_in[5];
    float* out = (float*)d_out;

    void *dQ, *dK, *dV, *dZ;
    cudaGetSymbolAddress(&dQ, g_Q);
    cudaGetSymbolAddress(&dK, g_K);
    cudaGetSymbolAddress(&dV, g_V);
    cudaGetSymbolAddress(&dZ, g_Zs);

    cudaFuncSetAttribute(attn_tc_kernel, cudaFuncAttributeMaxDynamicSharedMemorySize,
                         ATTN_SMEM);
    cudaFuncSetAttribute(gemm_tc_kernel, cudaFuncAttributeMaxDynamicSharedMemorySize,
                         GEMM_SMEM);

    dim3 gg(2, HWSZ / 128, BB);   // m-tile fastest -> B-tile L2 reuse

    gemm_tc_kernel<<<gg, 256, GEMM_SMEM>>>(WQ, x, nullptr, dQ, 1, 0);
    gemm_tc_kernel<<<gg, 256, GEMM_SMEM>>>(WK, y, nullptr, dK, 1, 0);
    gemm_tc_kernel<<<gg, 256, GEMM_SMEM>>>(WV, y, nullptr, dV, 1, 0);
    attn_tc_kernel<<<BB * CC, 224, ATTN_SMEM>>>((const uint32_t*)dQ,
                                                (const uint32_t*)dK,
                                                (const uint32_t*)dV,
                                                (float*)dZ);
    gemm_tc_kernel<<<gg, 256, GEMM_SMEM>>>(WZ, (const float*)dZ, x, out, 0, 1);
}